// round 1
// baseline (speedup 1.0000x reference)
#include <cuda_runtime.h>
#include <math.h>

// Problem constants
#define BB    8
#define SEQ   1024
#define CH    768
#define NH    12
#define HDIM  64
#define MROWS (BB*SEQ)      // 8192 token rows
#define C3    (3*CH)        // 2304
#define CQKV  (3*C3)        // 6912 (3 stages x 3C)
#define MLPH  (4*CH)        // 3072

// ---------------------------------------------------------------------------
// Scratch (static __device__ arrays — no runtime allocation allowed)
// ---------------------------------------------------------------------------
__device__ float g_h   [(size_t)MROWS * CH];     // LN output (reused for LN1 and LN2)
__device__ float g_qkv [(size_t)MROWS * CQKV];   // fused qkv for all 3 stages
__device__ float g_ocat[(size_t)MROWS * C3];     // attention outputs, stage-concatenated, focus-scaled
__device__ float g_x2  [(size_t)MROWS * CH];     // x + attn_out
__device__ float g_mlp [(size_t)MROWS * MLPH];   // gelu(mlp1)
__device__ float g_projw[(size_t)CH * C3];       // packed proj weights [c][s*768+k]
__device__ float g_bias2[CH];                    // sum_s focus[s]*proj_b[s]

// ---------------------------------------------------------------------------
// LayerNorm: one block per row of 768
// ---------------------------------------------------------------------------
__global__ void __launch_bounds__(256) ln_kernel(const float* __restrict__ x,
                                                 const float* __restrict__ w,
                                                 const float* __restrict__ b,
                                                 float* __restrict__ out)
{
    __shared__ float red[2][8];
    const int row = blockIdx.x;
    const float* xr = x + (size_t)row * CH;
    const int t = threadIdx.x;
    float v0 = xr[t], v1 = xr[t + 256], v2 = xr[t + 512];
    float s  = v0 + v1 + v2;
    float sq = v0*v0 + v1*v1 + v2*v2;
    #pragma unroll
    for (int o = 16; o > 0; o >>= 1) {
        s  += __shfl_xor_sync(0xffffffff, s,  o);
        sq += __shfl_xor_sync(0xffffffff, sq, o);
    }
    const int warp = t >> 5, lane = t & 31;
    if (lane == 0) { red[0][warp] = s; red[1][warp] = sq; }
    __syncthreads();
    if (warp == 0) {
        s = red[0][lane & 7]; sq = red[1][lane & 7];
        #pragma unroll
        for (int o = 4; o > 0; o >>= 1) {
            s  += __shfl_xor_sync(0xffffffff, s,  o);
            sq += __shfl_xor_sync(0xffffffff, sq, o);
        }
        if (lane == 0) { red[0][0] = s; red[1][0] = sq; }
    }
    __syncthreads();
    const float mu  = red[0][0] * (1.0f / CH);
    float var = red[1][0] * (1.0f / CH) - mu * mu;
    var = fmaxf(var, 0.0f);
    const float inv = rsqrtf(var + 1e-5f);
    float* orow = out + (size_t)row * CH;
    orow[t]       = (v0 - mu) * inv * w[t]       + b[t];
    orow[t + 256] = (v1 - mu) * inv * w[t + 256] + b[t + 256];
    orow[t + 512] = (v2 - mu) * inv * w[t + 512] + b[t + 512];
}

// ---------------------------------------------------------------------------
// Prepack: g_projw[c][s*768+k] = proj_w[s][c][k]; g_bias2[c] = sum focus*proj_b
// ---------------------------------------------------------------------------
__global__ void __launch_bounds__(256) prepack_kernel(const float* __restrict__ proj_w,
                                                      const float* __restrict__ proj_b,
                                                      const float* __restrict__ focus_w)
{
    const int idx = blockIdx.x * 256 + threadIdx.x;
    const int total = CH * C3;
    if (idx < total) {
        const int c   = idx / C3;
        const int rem = idx % C3;
        const int s   = rem / CH;
        const int k   = rem % CH;
        g_projw[idx] = proj_w[((size_t)s * CH + c) * CH + k];
    }
    if (idx < CH) {
        float acc = 0.0f;
        #pragma unroll
        for (int s = 0; s < 3; s++) acc += focus_w[s] * proj_b[s * CH + idx];
        g_bias2[idx] = acc;
    }
}

// ---------------------------------------------------------------------------
// GEMM: C[m,n] = sum_k A[m,k] * B[n,k]  (A row-major MxK, B row-major NxK)
// MODE 0: plain           MODE 1: + bias[n] + resid[m,n]     MODE 2: gelu(.+bias)
// Tiles: 128x128x8, 256 threads, 8x8 per-thread micro-tile. All dims tile-exact.
// ---------------------------------------------------------------------------
template<int MODE>
__global__ void __launch_bounds__(256) gemm_bt_kernel(
    const float* __restrict__ A, const float* __restrict__ B,
    const float* __restrict__ bias, const float* __restrict__ resid,
    float* __restrict__ C, int M, int N, int K)
{
    __shared__ float As[8][128];
    __shared__ float Bs[8][128];
    const int tid = threadIdx.x;
    const int bm = blockIdx.y * 128;
    const int bn = blockIdx.x * 128;
    const int tx = (tid & 15) * 8;   // n within tile
    const int ty = (tid >> 4) * 8;   // m within tile
    const int lr = tid >> 1;         // load row 0..127
    const int lc = (tid & 1) * 4;    // load k offset 0 or 4
    const float* Ap = A + (size_t)(bm + lr) * K + lc;
    const float* Bp = B + (size_t)(bn + lr) * K + lc;
    float acc[8][8] = {};
    for (int k0 = 0; k0 < K; k0 += 8) {
        float4 av = *(const float4*)(Ap + k0);
        float4 bv = *(const float4*)(Bp + k0);
        As[lc + 0][lr] = av.x; As[lc + 1][lr] = av.y;
        As[lc + 2][lr] = av.z; As[lc + 3][lr] = av.w;
        Bs[lc + 0][lr] = bv.x; Bs[lc + 1][lr] = bv.y;
        Bs[lc + 2][lr] = bv.z; Bs[lc + 3][lr] = bv.w;
        __syncthreads();
        #pragma unroll
        for (int k = 0; k < 8; k++) {
            float ar[8], br[8];
            #pragma unroll
            for (int i = 0; i < 8; i++) ar[i] = As[k][ty + i];
            #pragma unroll
            for (int j = 0; j < 8; j++) br[j] = Bs[k][tx + j];
            #pragma unroll
            for (int i = 0; i < 8; i++)
                #pragma unroll
                for (int j = 0; j < 8; j++)
                    acc[i][j] = fmaf(ar[i], br[j], acc[i][j]);
        }
        __syncthreads();
    }
    float bj[8];
    if (MODE != 0) {
        #pragma unroll
        for (int j = 0; j < 8; j++) bj[j] = bias[bn + tx + j];
    }
    #pragma unroll
    for (int i = 0; i < 8; i++) {
        const int m = bm + ty + i;
        float* crow = C + (size_t)m * N + bn + tx;
        const float* rrow = (MODE == 1) ? (resid + (size_t)m * N + bn + tx) : nullptr;
        float out[8];
        #pragma unroll
        for (int j = 0; j < 8; j++) {
            float v = acc[i][j];
            if (MODE != 0) v += bj[j];
            if (MODE == 2) v = 0.5f * v * (1.0f + erff(v * 0.70710678118654752f));
            if (MODE == 1) v += rrow[j];
            out[j] = v;
        }
        *(float4*)(crow)     = make_float4(out[0], out[1], out[2], out[3]);
        *(float4*)(crow + 4) = make_float4(out[4], out[5], out[6], out[7]);
    }
}

// ---------------------------------------------------------------------------
// Flash attention: 1 thread = 1 query row. K/V tiles (64 keys x 64 dims) in SMEM,
// broadcast reads, online softmax in 16-key subchunks.
// grid: (SEQ/128, B*H, STAGES), block: 128
// Writes focus_w[s]-scaled output into g_ocat[m, s*768 + h*64 + d].
// ---------------------------------------------------------------------------
#define KT 64
__global__ void __launch_bounds__(128) attn_kernel(
    const float* __restrict__ qkv, const float* __restrict__ focus_w,
    float* __restrict__ ocat)
{
    __shared__ float Ks[KT][HDIM];
    __shared__ float Vs[KT][HDIM];
    const int s  = blockIdx.z;
    const int b  = blockIdx.y / NH;
    const int hh = blockIdx.y % NH;
    const int t  = threadIdx.x;
    const int m  = b * SEQ + blockIdx.x * 128 + t;

    // q row (64 floats) in registers
    float q[HDIM];
    {
        const float4* qp = (const float4*)(qkv + (size_t)m * CQKV + s * C3 + hh * HDIM);
        #pragma unroll
        for (int i = 0; i < 16; i++) {
            float4 v = qp[i];
            q[4*i] = v.x; q[4*i+1] = v.y; q[4*i+2] = v.z; q[4*i+3] = v.w;
        }
    }
    float o[HDIM];
    #pragma unroll
    for (int d = 0; d < HDIM; d++) o[d] = 0.0f;
    float mrun = -1e30f, lrun = 0.0f;
    const float scale = 0.125f;  // HD^-0.5
    const size_t kbase = (size_t)b * SEQ * CQKV + s * C3 + CH + hh * HDIM;

    for (int kt = 0; kt < SEQ; kt += KT) {
        // cooperative K/V tile load (coalesced float4)
        for (int i = t; i < KT * 16; i += 128) {
            const int row = i >> 4, d4 = i & 15;
            const size_t off = kbase + (size_t)(kt + row) * CQKV + d4 * 4;
            ((float4*)&Ks[row][0])[d4] = *(const float4*)(qkv + off);
            ((float4*)&Vs[row][0])[d4] = *(const float4*)(qkv + off + CH);
        }
        __syncthreads();
        #pragma unroll 1
        for (int sub = 0; sub < KT; sub += 16) {
            float sc[16];
            #pragma unroll
            for (int kk = 0; kk < 16; kk++) {
                const float4* Kr = (const float4*)&Ks[sub + kk][0];
                float a0 = 0, a1 = 0, a2 = 0, a3 = 0;
                #pragma unroll
                for (int d4 = 0; d4 < 16; d4++) {
                    float4 kv = Kr[d4];
                    a0 = fmaf(q[4*d4],   kv.x, a0);
                    a1 = fmaf(q[4*d4+1], kv.y, a1);
                    a2 = fmaf(q[4*d4+2], kv.z, a2);
                    a3 = fmaf(q[4*d4+3], kv.w, a3);
                }
                sc[kk] = (a0 + a1 + a2 + a3) * scale;
            }
            float mt = sc[0];
            #pragma unroll
            for (int kk = 1; kk < 16; kk++) mt = fmaxf(mt, sc[kk]);
            const float mnew = fmaxf(mrun, mt);
            const float alpha = __expf(mrun - mnew);
            lrun *= alpha;
            #pragma unroll
            for (int d = 0; d < HDIM; d++) o[d] *= alpha;
            #pragma unroll
            for (int kk = 0; kk < 16; kk++) {
                const float p = __expf(sc[kk] - mnew);
                lrun += p;
                const float4* Vr = (const float4*)&Vs[sub + kk][0];
                #pragma unroll
                for (int d4 = 0; d4 < 16; d4++) {
                    float4 vv = Vr[d4];
                    o[4*d4]   = fmaf(p, vv.x, o[4*d4]);
                    o[4*d4+1] = fmaf(p, vv.y, o[4*d4+1]);
                    o[4*d4+2] = fmaf(p, vv.z, o[4*d4+2]);
                    o[4*d4+3] = fmaf(p, vv.w, o[4*d4+3]);
                }
            }
            mrun = mnew;
        }
        __syncthreads();
    }
    const float f = focus_w[s] / lrun;
    float4* dst = (float4*)(ocat + (size_t)m * C3 + s * CH + hh * HDIM);
    #pragma unroll
    for (int d4 = 0; d4 < 16; d4++)
        dst[d4] = make_float4(o[4*d4]*f, o[4*d4+1]*f, o[4*d4+2]*f, o[4*d4+3]*f);
}

// ---------------------------------------------------------------------------
// Launch
// ---------------------------------------------------------------------------
extern "C" void kernel_launch(void* const* d_in, const int* in_sizes, int n_in,
                              void* d_out, int out_size)
{
    const float* x      = (const float*)d_in[0];
    const float* qkv_w  = (const float*)d_in[1];   // [3, 2304, 768] == [6912, 768]
    const float* proj_w = (const float*)d_in[2];   // [3, 768, 768]
    const float* proj_b = (const float*)d_in[3];   // [3, 768]
    const float* ln1_w  = (const float*)d_in[4];
    const float* ln1_b  = (const float*)d_in[5];
    const float* ln2_w  = (const float*)d_in[6];
    const float* ln2_b  = (const float*)d_in[7];
    const float* mlp_w1 = (const float*)d_in[8];   // [3072, 768]
    const float* mlp_b1 = (const float*)d_in[9];
    const float* mlp_w2 = (const float*)d_in[10];  // [768, 3072]
    const float* mlp_b2 = (const float*)d_in[11];
    const float* focus  = (const float*)d_in[12];  // [3]
    float* out = (float*)d_out;

    float *h, *qkvb, *ocat, *x2, *mlp, *pw, *b2;
    cudaGetSymbolAddress((void**)&h,    g_h);
    cudaGetSymbolAddress((void**)&qkvb, g_qkv);
    cudaGetSymbolAddress((void**)&ocat, g_ocat);
    cudaGetSymbolAddress((void**)&x2,   g_x2);
    cudaGetSymbolAddress((void**)&mlp,  g_mlp);
    cudaGetSymbolAddress((void**)&pw,   g_projw);
    cudaGetSymbolAddress((void**)&b2,   g_bias2);

    // 1) h = LN1(x)
    ln_kernel<<<MROWS, 256>>>(x, ln1_w, ln1_b, h);
    // 2) pack proj weights/bias (independent of (1), same stream anyway)
    prepack_kernel<<<(CH * C3 + 255) / 256, 256>>>(proj_w, proj_b, focus);
    // 3) qkv = h @ qkv_w^T for all 3 stages at once  (8192 x 6912 x 768)
    gemm_bt_kernel<0><<<dim3(CQKV / 128, MROWS / 128), 256>>>(
        h, qkv_w, nullptr, nullptr, qkvb, MROWS, CQKV, CH);
    // 4) attention per (stage, b, head), focus-scaled outputs concatenated
    attn_kernel<<<dim3(SEQ / 128, BB * NH, 3), 128>>>(qkvb, focus, ocat);
    // 5) x2 = x + ocat @ projw_cat^T + bias2   (8192 x 768 x 2304)
    gemm_bt_kernel<1><<<dim3(CH / 128, MROWS / 128), 256>>>(
        ocat, pw, b2, x, x2, MROWS, CH, C3);
    // 6) h = LN2(x2)
    ln_kernel<<<MROWS, 256>>>(x2, ln2_w, ln2_b, h);
    // 7) mlp = gelu(h @ mlp_w1^T + b1)   (8192 x 3072 x 768)
    gemm_bt_kernel<2><<<dim3(MLPH / 128, MROWS / 128), 256>>>(
        h, mlp_w1, mlp_b1, nullptr, mlp, MROWS, MLPH, CH);
    // 8) out = x2 + mlp @ mlp_w2^T + b2   (8192 x 768 x 3072)
    gemm_bt_kernel<1><<<dim3(CH / 128, MROWS / 128), 256>>>(
        mlp, mlp_w2, mlp_b2, x2, out, MROWS, CH, MLPH);
}

// round 3
// speedup vs baseline: 1.7101x; 1.7101x over previous
#include <cuda_runtime.h>
#include <cuda_bf16.h>
#include <math.h>
#include <stdint.h>

// Problem constants
#define BB    8
#define SEQ   1024
#define CH    768
#define NH    12
#define HDIM  64
#define MROWS (BB*SEQ)      // 8192 token rows
#define C3    (3*CH)        // 2304
#define CQKV  (3*C3)        // 6912
#define MLPH  (4*CH)        // 3072

// ---------------------------------------------------------------------------
// Scratch (static __device__ arrays)
// ---------------------------------------------------------------------------
__device__ float g_h   [(size_t)MROWS * CH];
__device__ float g_qkv [(size_t)MROWS * CQKV];
__device__ float g_ocat[(size_t)MROWS * C3];
__device__ float g_x2  [(size_t)MROWS * CH];
__device__ float g_mlp [(size_t)MROWS * MLPH];
__device__ float g_projw[(size_t)CH * C3];
__device__ float g_bias2[CH];

// ---------------------------------------------------------------------------
// mma.sync helpers (sm_80-level PTX — compiles for plain sm_100)
// ---------------------------------------------------------------------------
__device__ __forceinline__ uint32_t smem_u32(const void* p) {
    uint32_t a;
    asm("{ .reg .u64 t; cvta.to.shared.u64 t, %1; cvt.u32.u64 %0, t; }" : "=r"(a) : "l"(p));
    return a;
}
__device__ __forceinline__ void ldsm4(uint32_t* r, uint32_t addr) {
    asm volatile("ldmatrix.sync.aligned.m8n8.x4.shared.b16 {%0,%1,%2,%3}, [%4];"
        : "=r"(r[0]), "=r"(r[1]), "=r"(r[2]), "=r"(r[3]) : "r"(addr));
}
__device__ __forceinline__ void ldsm2(uint32_t* r, uint32_t addr) {
    asm volatile("ldmatrix.sync.aligned.m8n8.x2.shared.b16 {%0,%1}, [%2];"
        : "=r"(r[0]), "=r"(r[1]) : "r"(addr));
}
__device__ __forceinline__ void mma16816(float* c, const uint32_t* a, const uint32_t* b) {
    asm volatile(
        "mma.sync.aligned.m16n8k16.row.col.f32.bf16.bf16.f32 "
        "{%0,%1,%2,%3}, {%4,%5,%6,%7}, {%8,%9}, {%0,%1,%2,%3};"
        : "+f"(c[0]), "+f"(c[1]), "+f"(c[2]), "+f"(c[3])
        : "r"(a[0]), "r"(a[1]), "r"(a[2]), "r"(a[3]), "r"(b[0]), "r"(b[1]));
}

// ---------------------------------------------------------------------------
// LayerNorm
// ---------------------------------------------------------------------------
__global__ void __launch_bounds__(256) ln_kernel(const float* __restrict__ x,
                                                 const float* __restrict__ w,
                                                 const float* __restrict__ b,
                                                 float* __restrict__ out)
{
    __shared__ float red[2][8];
    const int row = blockIdx.x;
    const float* xr = x + (size_t)row * CH;
    const int t = threadIdx.x;
    float v0 = xr[t], v1 = xr[t + 256], v2 = xr[t + 512];
    float s  = v0 + v1 + v2;
    float sq = v0*v0 + v1*v1 + v2*v2;
    #pragma unroll
    for (int o = 16; o > 0; o >>= 1) {
        s  += __shfl_xor_sync(0xffffffff, s,  o);
        sq += __shfl_xor_sync(0xffffffff, sq, o);
    }
    const int warp = t >> 5, lane = t & 31;
    if (lane == 0) { red[0][warp] = s; red[1][warp] = sq; }
    __syncthreads();
    if (warp == 0) {
        s = red[0][lane & 7]; sq = red[1][lane & 7];
        #pragma unroll
        for (int o = 4; o > 0; o >>= 1) {
            s  += __shfl_xor_sync(0xffffffff, s,  o);
            sq += __shfl_xor_sync(0xffffffff, sq, o);
        }
        if (lane == 0) { red[0][0] = s; red[1][0] = sq; }
    }
    __syncthreads();
    const float mu  = red[0][0] * (1.0f / CH);
    float var = red[1][0] * (1.0f / CH) - mu * mu;
    var = fmaxf(var, 0.0f);
    const float inv = rsqrtf(var + 1e-5f);
    float* orow = out + (size_t)row * CH;
    orow[t]       = (v0 - mu) * inv * w[t]       + b[t];
    orow[t + 256] = (v1 - mu) * inv * w[t + 256] + b[t + 256];
    orow[t + 512] = (v2 - mu) * inv * w[t + 512] + b[t + 512];
}

// ---------------------------------------------------------------------------
// Prepack proj weights/bias
// ---------------------------------------------------------------------------
__global__ void __launch_bounds__(256) prepack_kernel(const float* __restrict__ proj_w,
                                                      const float* __restrict__ proj_b,
                                                      const float* __restrict__ focus_w)
{
    const int idx = blockIdx.x * 256 + threadIdx.x;
    const int total = CH * C3;
    if (idx < total) {
        const int c   = idx / C3;
        const int rem = idx % C3;
        const int s   = rem / CH;
        const int k   = rem % CH;
        g_projw[idx] = proj_w[((size_t)s * CH + c) * CH + k];
    }
    if (idx < CH) {
        float acc = 0.0f;
        #pragma unroll
        for (int s = 0; s < 3; s++) acc += focus_w[s] * proj_b[s * CH + idx];
        g_bias2[idx] = acc;
    }
}

// ---------------------------------------------------------------------------
// Tensor-core GEMM: C[m,n] = sum_k A[m,k]*B[n,k]   (both row-major, B as NxK)
// Split-bf16: x = hi + lo;  C ≈ Ahi*Bhi + Ahi*Blo + Alo*Bhi (fp32 accum).
// Tile 128x128, Kc=32, 256 threads = 8 warps (2m x 4n), warp tile 64x32.
// smem rows padded to 80B so ldmatrix (r*80 mod 128) is conflict-free.
// MODE 0: plain   MODE 1: +bias[n]+resid   MODE 2: gelu(.+bias)
// ---------------------------------------------------------------------------
#define PITCH_B 80          // bytes per 32-col bf16 row (64B data + 16B pad)
#define MAT_SM  (128 * PITCH_B)

__device__ __forceinline__ void split_store(float4 v, char* hi, char* lo, uint32_t off) {
    __nv_bfloat16 h0 = __float2bfloat16(v.x), h1 = __float2bfloat16(v.y);
    __nv_bfloat16 h2 = __float2bfloat16(v.z), h3 = __float2bfloat16(v.w);
    float l0 = v.x - __bfloat162float(h0), l1 = v.y - __bfloat162float(h1);
    float l2 = v.z - __bfloat162float(h2), l3 = v.w - __bfloat162float(h3);
    __nv_bfloat162 hp0 = __halves2bfloat162(h0, h1), hp1 = __halves2bfloat162(h2, h3);
    __nv_bfloat162 lp0 = __floats2bfloat162_rn(l0, l1), lp1 = __floats2bfloat162_rn(l2, l3);
    *(uint2*)(hi + off) = make_uint2(*(uint32_t*)&hp0, *(uint32_t*)&hp1);
    *(uint2*)(lo + off) = make_uint2(*(uint32_t*)&lp0, *(uint32_t*)&lp1);
}

template<int MODE>
__global__ void __launch_bounds__(256, 2) gemm_tc_kernel(
    const float* __restrict__ A, const float* __restrict__ B,
    const float* __restrict__ bias, const float* __restrict__ resid,
    float* __restrict__ C, int M, int N, int K)
{
    __shared__ __align__(16) char smem[4 * MAT_SM];   // Ahi, Alo, Bhi, Blo
    char* sAhi = smem;
    char* sAlo = smem + MAT_SM;
    char* sBhi = smem + 2 * MAT_SM;
    char* sBlo = smem + 3 * MAT_SM;
    const uint32_t sb = smem_u32(smem);

    const int tid  = threadIdx.x;
    const int lane = tid & 31;
    const int wid  = tid >> 5;
    const int wm   = wid >> 2;       // 0..1
    const int wn   = wid & 3;        // 0..3
    const int bm = blockIdx.y * 128;
    const int bn = blockIdx.x * 128;

    float acc[4][4][4];
    #pragma unroll
    for (int i = 0; i < 4; i++)
        #pragma unroll
        for (int j = 0; j < 4; j++)
            #pragma unroll
            for (int q = 0; q < 4; q++) acc[i][j][q] = 0.0f;

    // ldmatrix base offsets (byte addresses within each matrix)
    const uint32_t a_off = (uint32_t)(wm * 64 + (lane & 15)) * PITCH_B + (lane >> 4) * 16;
    const uint32_t b_off = (uint32_t)(wn * 32 + (lane & 7)) * PITCH_B + ((lane >> 3) & 1) * 16;

    for (int k0 = 0; k0 < K; k0 += 32) {
        // ---- load + split-convert A and B tiles (128 x 32 f32 each) ----
        {
            const float* srcA = A + (size_t)bm * K + k0;
            const float* srcB = B + (size_t)bn * K + k0;
            #pragma unroll
            for (int it = 0; it < 4; it++) {
                const int idx = tid + it * 256;
                const int r = idx >> 3, c4 = idx & 7;
                const uint32_t off = (uint32_t)r * PITCH_B + c4 * 8;
                split_store(*(const float4*)(srcA + (size_t)r * K + c4 * 4), sAhi, sAlo, off);
                split_store(*(const float4*)(srcB + (size_t)r * K + c4 * 4), sBhi, sBlo, off);
            }
        }
        __syncthreads();
        // ---- 2 k-steps of 16, three split passes each ----
        #pragma unroll
        for (int ks = 0; ks < 2; ks++) {
            const uint32_t kso = ks * 32;
            uint32_t af[4][4], bf[4][2];
            // pass 1: Ahi * Bhi
            #pragma unroll
            for (int am = 0; am < 4; am++)
                ldsm4(af[am], sb + 0 * MAT_SM + a_off + kso + am * 16 * PITCH_B);
            #pragma unroll
            for (int an = 0; an < 4; an++)
                ldsm2(bf[an], sb + 2 * MAT_SM + b_off + kso + an * 8 * PITCH_B);
            #pragma unroll
            for (int am = 0; am < 4; am++)
                #pragma unroll
                for (int an = 0; an < 4; an++)
                    mma16816(acc[am][an], af[am], bf[an]);
            // pass 2: Ahi * Blo
            #pragma unroll
            for (int an = 0; an < 4; an++)
                ldsm2(bf[an], sb + 3 * MAT_SM + b_off + kso + an * 8 * PITCH_B);
            #pragma unroll
            for (int am = 0; am < 4; am++)
                #pragma unroll
                for (int an = 0; an < 4; an++)
                    mma16816(acc[am][an], af[am], bf[an]);
            // pass 3: Alo * Bhi
            #pragma unroll
            for (int am = 0; am < 4; am++)
                ldsm4(af[am], sb + 1 * MAT_SM + a_off + kso + am * 16 * PITCH_B);
            #pragma unroll
            for (int an = 0; an < 4; an++)
                ldsm2(bf[an], sb + 2 * MAT_SM + b_off + kso + an * 8 * PITCH_B);
            #pragma unroll
            for (int am = 0; am < 4; am++)
                #pragma unroll
                for (int an = 0; an < 4; an++)
                    mma16816(acc[am][an], af[am], bf[an]);
        }
        __syncthreads();
    }

    // ---- epilogue ----
    #pragma unroll
    for (int am = 0; am < 4; am++) {
        const int r0 = bm + wm * 64 + am * 16 + (lane >> 2);
        #pragma unroll
        for (int rr = 0; rr < 2; rr++) {
            const int r = r0 + rr * 8;
            float* crow = C + (size_t)r * N;
            const float* rrow = (MODE == 1) ? (resid + (size_t)r * N) : nullptr;
            #pragma unroll
            for (int an = 0; an < 4; an++) {
                const int col = bn + wn * 32 + an * 8 + 2 * (lane & 3);
                float v0 = acc[am][an][rr * 2 + 0];
                float v1 = acc[am][an][rr * 2 + 1];
                if (MODE != 0) { v0 += bias[col]; v1 += bias[col + 1]; }
                if (MODE == 2) {
                    v0 = 0.5f * v0 * (1.0f + erff(v0 * 0.70710678118654752f));
                    v1 = 0.5f * v1 * (1.0f + erff(v1 * 0.70710678118654752f));
                }
                if (MODE == 1) { v0 += rrow[col]; v1 += rrow[col + 1]; }
                *(float2*)(crow + col) = make_float2(v0, v1);
            }
        }
    }
}

// ---------------------------------------------------------------------------
// Flash attention (SIMT, validated round-1): 1 thread = 1 query row.
// ---------------------------------------------------------------------------
#define KT 64
__global__ void __launch_bounds__(128) attn_kernel(
    const float* __restrict__ qkv, const float* __restrict__ focus_w,
    float* __restrict__ ocat)
{
    __shared__ float Ks[KT][HDIM];
    __shared__ float Vs[KT][HDIM];
    const int s  = blockIdx.z;
    const int b  = blockIdx.y / NH;
    const int hh = blockIdx.y % NH;
    const int t  = threadIdx.x;
    const int m  = b * SEQ + blockIdx.x * 128 + t;

    float q[HDIM];
    {
        const float4* qp = (const float4*)(qkv + (size_t)m * CQKV + s * C3 + hh * HDIM);
        #pragma unroll
        for (int i = 0; i < 16; i++) {
            float4 v = qp[i];
            q[4*i] = v.x; q[4*i+1] = v.y; q[4*i+2] = v.z; q[4*i+3] = v.w;
        }
    }
    float o[HDIM];
    #pragma unroll
    for (int d = 0; d < HDIM; d++) o[d] = 0.0f;
    float mrun = -1e30f, lrun = 0.0f;
    const float scale = 0.125f;
    const size_t kbase = (size_t)b * SEQ * CQKV + s * C3 + CH + hh * HDIM;

    for (int kt = 0; kt < SEQ; kt += KT) {
        for (int i = t; i < KT * 16; i += 128) {
            const int row = i >> 4, d4 = i & 15;
            const size_t off = kbase + (size_t)(kt + row) * CQKV + d4 * 4;
            ((float4*)&Ks[row][0])[d4] = *(const float4*)(qkv + off);
            ((float4*)&Vs[row][0])[d4] = *(const float4*)(qkv + off + CH);
        }
        __syncthreads();
        #pragma unroll 1
        for (int sub = 0; sub < KT; sub += 16) {
            float sc[16];
            #pragma unroll
            for (int kk = 0; kk < 16; kk++) {
                const float4* Kr = (const float4*)&Ks[sub + kk][0];
                float a0 = 0, a1 = 0, a2 = 0, a3 = 0;
                #pragma unroll
                for (int d4 = 0; d4 < 16; d4++) {
                    float4 kv = Kr[d4];
                    a0 = fmaf(q[4*d4],   kv.x, a0);
                    a1 = fmaf(q[4*d4+1], kv.y, a1);
                    a2 = fmaf(q[4*d4+2], kv.z, a2);
                    a3 = fmaf(q[4*d4+3], kv.w, a3);
                }
                sc[kk] = (a0 + a1 + a2 + a3) * scale;
            }
            float mt = sc[0];
            #pragma unroll
            for (int kk = 1; kk < 16; kk++) mt = fmaxf(mt, sc[kk]);
            const float mnew = fmaxf(mrun, mt);
            const float alpha = __expf(mrun - mnew);
            lrun *= alpha;
            #pragma unroll
            for (int d = 0; d < HDIM; d++) o[d] *= alpha;
            #pragma unroll
            for (int kk = 0; kk < 16; kk++) {
                const float p = __expf(sc[kk] - mnew);
                lrun += p;
                const float4* Vr = (const float4*)&Vs[sub + kk][0];
                #pragma unroll
                for (int d4 = 0; d4 < 16; d4++) {
                    float4 vv = Vr[d4];
                    o[4*d4]   = fmaf(p, vv.x, o[4*d4]);
                    o[4*d4+1] = fmaf(p, vv.y, o[4*d4+1]);
                    o[4*d4+2] = fmaf(p, vv.z, o[4*d4+2]);
                    o[4*d4+3] = fmaf(p, vv.w, o[4*d4+3]);
                }
            }
            mrun = mnew;
        }
        __syncthreads();
    }
    const float f = focus_w[s] / lrun;
    float4* dst = (float4*)(ocat + (size_t)m * C3 + s * CH + hh * HDIM);
    #pragma unroll
    for (int d4 = 0; d4 < 16; d4++)
        dst[d4] = make_float4(o[4*d4]*f, o[4*d4+1]*f, o[4*d4+2]*f, o[4*d4+3]*f);
}

// ---------------------------------------------------------------------------
// Launch
// ---------------------------------------------------------------------------
extern "C" void kernel_launch(void* const* d_in, const int* in_sizes, int n_in,
                              void* d_out, int out_size)
{
    const float* x      = (const float*)d_in[0];
    const float* qkv_w  = (const float*)d_in[1];
    const float* proj_w = (const float*)d_in[2];
    const float* proj_b = (const float*)d_in[3];
    const float* ln1_w  = (const float*)d_in[4];
    const float* ln1_b  = (const float*)d_in[5];
    const float* ln2_w  = (const float*)d_in[6];
    const float* ln2_b  = (const float*)d_in[7];
    const float* mlp_w1 = (const float*)d_in[8];
    const float* mlp_b1 = (const float*)d_in[9];
    const float* mlp_w2 = (const float*)d_in[10];
    const float* mlp_b2 = (const float*)d_in[11];
    const float* focus  = (const float*)d_in[12];
    float* out = (float*)d_out;

    float *h, *qkvb, *ocat, *x2, *mlp, *pw, *b2;
    cudaGetSymbolAddress((void**)&h,    g_h);
    cudaGetSymbolAddress((void**)&qkvb, g_qkv);
    cudaGetSymbolAddress((void**)&ocat, g_ocat);
    cudaGetSymbolAddress((void**)&x2,   g_x2);
    cudaGetSymbolAddress((void**)&mlp,  g_mlp);
    cudaGetSymbolAddress((void**)&pw,   g_projw);
    cudaGetSymbolAddress((void**)&b2,   g_bias2);

    // 1) h = LN1(x)
    ln_kernel<<<MROWS, 256>>>(x, ln1_w, ln1_b, h);
    // 2) pack proj weights/bias
    prepack_kernel<<<(CH * C3 + 255) / 256, 256>>>(proj_w, proj_b, focus);
    // 3) qkv = h @ qkv_w^T  (8192 x 6912 x 768)
    gemm_tc_kernel<0><<<dim3(CQKV / 128, MROWS / 128), 256>>>(
        h, qkv_w, nullptr, nullptr, qkvb, MROWS, CQKV, CH);
    // 4) attention
    attn_kernel<<<dim3(SEQ / 128, BB * NH, 3), 128>>>(qkvb, focus, ocat);
    // 5) x2 = x + ocat @ projw_cat^T + bias2  (8192 x 768 x 2304)
    gemm_tc_kernel<1><<<dim3(CH / 128, MROWS / 128), 256>>>(
        ocat, pw, b2, x, x2, MROWS, CH, C3);
    // 6) h = LN2(x2)
    ln_kernel<<<MROWS, 256>>>(x2, ln2_w, ln2_b, h);
    // 7) mlp = gelu(h @ mlp_w1^T + b1)  (8192 x 3072 x 768)
    gemm_tc_kernel<2><<<dim3(MLPH / 128, MROWS / 128), 256>>>(
        h, mlp_w1, mlp_b1, nullptr, mlp, MROWS, MLPH, CH);
    // 8) out = x2 + mlp @ mlp_w2^T + b2  (8192 x 768 x 3072)
    gemm_tc_kernel<1><<<dim3(CH / 128, MROWS / 128), 256>>>(
        mlp, mlp_w2, mlp_b2, x2, out, MROWS, CH, MLPH);
}

// round 4
// speedup vs baseline: 3.5859x; 2.0969x over previous
#include <cuda_runtime.h>
#include <cuda_bf16.h>
#include <math.h>
#include <stdint.h>

// Problem constants
#define BB    8
#define SEQ   1024
#define CH    768
#define NH    12
#define HDIM  64
#define MROWS (BB*SEQ)      // 8192 token rows
#define C3    (3*CH)        // 2304
#define CQKV  (3*C3)        // 6912
#define MLPH  (4*CH)        // 3072

// ---------------------------------------------------------------------------
// Scratch
// ---------------------------------------------------------------------------
__device__ float g_h   [(size_t)MROWS * CH];
__device__ float g_qkv [(size_t)MROWS * CQKV];
__device__ float g_ocat[(size_t)MROWS * C3];
__device__ float g_x2  [(size_t)MROWS * CH];
__device__ float g_mlp [(size_t)MROWS * MLPH];
__device__ float g_projw[(size_t)CH * C3];
__device__ float g_bias2[CH];

// ---------------------------------------------------------------------------
// mma.sync helpers (sm_80-level PTX — compiles for plain sm_100)
// ---------------------------------------------------------------------------
__device__ __forceinline__ uint32_t smem_u32(const void* p) {
    uint32_t a;
    asm("{ .reg .u64 t; cvta.to.shared.u64 t, %1; cvt.u32.u64 %0, t; }" : "=r"(a) : "l"(p));
    return a;
}
__device__ __forceinline__ void ldsm4(uint32_t* r, uint32_t addr) {
    asm volatile("ldmatrix.sync.aligned.m8n8.x4.shared.b16 {%0,%1,%2,%3}, [%4];"
        : "=r"(r[0]), "=r"(r[1]), "=r"(r[2]), "=r"(r[3]) : "r"(addr));
}
__device__ __forceinline__ void ldsm4t(uint32_t* r, uint32_t addr) {
    asm volatile("ldmatrix.sync.aligned.m8n8.x4.trans.shared.b16 {%0,%1,%2,%3}, [%4];"
        : "=r"(r[0]), "=r"(r[1]), "=r"(r[2]), "=r"(r[3]) : "r"(addr));
}
__device__ __forceinline__ void ldsm2(uint32_t* r, uint32_t addr) {
    asm volatile("ldmatrix.sync.aligned.m8n8.x2.shared.b16 {%0,%1}, [%2];"
        : "=r"(r[0]), "=r"(r[1]) : "r"(addr));
}
__device__ __forceinline__ void mma16816(float* c, const uint32_t* a, const uint32_t* b) {
    asm volatile(
        "mma.sync.aligned.m16n8k16.row.col.f32.bf16.bf16.f32 "
        "{%0,%1,%2,%3}, {%4,%5,%6,%7}, {%8,%9}, {%0,%1,%2,%3};"
        : "+f"(c[0]), "+f"(c[1]), "+f"(c[2]), "+f"(c[3])
        : "r"(a[0]), "r"(a[1]), "r"(a[2]), "r"(a[3]), "r"(b[0]), "r"(b[1]));
}
__device__ __forceinline__ uint32_t pack_bf16x2(float lo, float hi) {
    __nv_bfloat162 p = __floats2bfloat162_rn(lo, hi);
    return *(uint32_t*)&p;
}

// ---------------------------------------------------------------------------
// LayerNorm
// ---------------------------------------------------------------------------
__global__ void __launch_bounds__(256) ln_kernel(const float* __restrict__ x,
                                                 const float* __restrict__ w,
                                                 const float* __restrict__ b,
                                                 float* __restrict__ out)
{
    __shared__ float red[2][8];
    const int row = blockIdx.x;
    const float* xr = x + (size_t)row * CH;
    const int t = threadIdx.x;
    float v0 = xr[t], v1 = xr[t + 256], v2 = xr[t + 512];
    float s  = v0 + v1 + v2;
    float sq = v0*v0 + v1*v1 + v2*v2;
    #pragma unroll
    for (int o = 16; o > 0; o >>= 1) {
        s  += __shfl_xor_sync(0xffffffff, s,  o);
        sq += __shfl_xor_sync(0xffffffff, sq, o);
    }
    const int warp = t >> 5, lane = t & 31;
    if (lane == 0) { red[0][warp] = s; red[1][warp] = sq; }
    __syncthreads();
    if (warp == 0) {
        s = red[0][lane & 7]; sq = red[1][lane & 7];
        #pragma unroll
        for (int o = 4; o > 0; o >>= 1) {
            s  += __shfl_xor_sync(0xffffffff, s,  o);
            sq += __shfl_xor_sync(0xffffffff, sq, o);
        }
        if (lane == 0) { red[0][0] = s; red[1][0] = sq; }
    }
    __syncthreads();
    const float mu  = red[0][0] * (1.0f / CH);
    float var = red[1][0] * (1.0f / CH) - mu * mu;
    var = fmaxf(var, 0.0f);
    const float inv = rsqrtf(var + 1e-5f);
    float* orow = out + (size_t)row * CH;
    orow[t]       = (v0 - mu) * inv * w[t]       + b[t];
    orow[t + 256] = (v1 - mu) * inv * w[t + 256] + b[t + 256];
    orow[t + 512] = (v2 - mu) * inv * w[t + 512] + b[t + 512];
}

// ---------------------------------------------------------------------------
// Prepack proj weights/bias
// ---------------------------------------------------------------------------
__global__ void __launch_bounds__(256) prepack_kernel(const float* __restrict__ proj_w,
                                                      const float* __restrict__ proj_b,
                                                      const float* __restrict__ focus_w)
{
    const int idx = blockIdx.x * 256 + threadIdx.x;
    const int total = CH * C3;
    if (idx < total) {
        const int c   = idx / C3;
        const int rem = idx % C3;
        const int s   = rem / CH;
        const int k   = rem % CH;
        g_projw[idx] = proj_w[((size_t)s * CH + c) * CH + k];
    }
    if (idx < CH) {
        float acc = 0.0f;
        #pragma unroll
        for (int s = 0; s < 3; s++) acc += focus_w[s] * proj_b[s * CH + idx];
        g_bias2[idx] = acc;
    }
}

// ---------------------------------------------------------------------------
// Tensor-core GEMM (validated round-3): split-bf16, tile 128x128, Kc=32.
// ---------------------------------------------------------------------------
#define PITCH_B 80
#define MAT_SM  (128 * PITCH_B)

__device__ __forceinline__ void split_store(float4 v, char* hi, char* lo, uint32_t off) {
    __nv_bfloat16 h0 = __float2bfloat16(v.x), h1 = __float2bfloat16(v.y);
    __nv_bfloat16 h2 = __float2bfloat16(v.z), h3 = __float2bfloat16(v.w);
    float l0 = v.x - __bfloat162float(h0), l1 = v.y - __bfloat162float(h1);
    float l2 = v.z - __bfloat162float(h2), l3 = v.w - __bfloat162float(h3);
    __nv_bfloat162 hp0 = __halves2bfloat162(h0, h1), hp1 = __halves2bfloat162(h2, h3);
    __nv_bfloat162 lp0 = __floats2bfloat162_rn(l0, l1), lp1 = __floats2bfloat162_rn(l2, l3);
    *(uint2*)(hi + off) = make_uint2(*(uint32_t*)&hp0, *(uint32_t*)&hp1);
    *(uint2*)(lo + off) = make_uint2(*(uint32_t*)&lp0, *(uint32_t*)&lp1);
}

template<int MODE>
__global__ void __launch_bounds__(256, 2) gemm_tc_kernel(
    const float* __restrict__ A, const float* __restrict__ B,
    const float* __restrict__ bias, const float* __restrict__ resid,
    float* __restrict__ C, int M, int N, int K)
{
    __shared__ __align__(16) char smem[4 * MAT_SM];
    char* sAhi = smem;
    char* sAlo = smem + MAT_SM;
    char* sBhi = smem + 2 * MAT_SM;
    char* sBlo = smem + 3 * MAT_SM;
    const uint32_t sb = smem_u32(smem);

    const int tid  = threadIdx.x;
    const int lane = tid & 31;
    const int wid  = tid >> 5;
    const int wm   = wid >> 2;
    const int wn   = wid & 3;
    const int bm = blockIdx.y * 128;
    const int bn = blockIdx.x * 128;

    float acc[4][4][4];
    #pragma unroll
    for (int i = 0; i < 4; i++)
        #pragma unroll
        for (int j = 0; j < 4; j++)
            #pragma unroll
            for (int q = 0; q < 4; q++) acc[i][j][q] = 0.0f;

    const uint32_t a_off = (uint32_t)(wm * 64 + (lane & 15)) * PITCH_B + (lane >> 4) * 16;
    const uint32_t b_off = (uint32_t)(wn * 32 + (lane & 7)) * PITCH_B + ((lane >> 3) & 1) * 16;

    for (int k0 = 0; k0 < K; k0 += 32) {
        {
            const float* srcA = A + (size_t)bm * K + k0;
            const float* srcB = B + (size_t)bn * K + k0;
            #pragma unroll
            for (int it = 0; it < 4; it++) {
                const int idx = tid + it * 256;
                const int r = idx >> 3, c4 = idx & 7;
                const uint32_t off = (uint32_t)r * PITCH_B + c4 * 8;
                split_store(*(const float4*)(srcA + (size_t)r * K + c4 * 4), sAhi, sAlo, off);
                split_store(*(const float4*)(srcB + (size_t)r * K + c4 * 4), sBhi, sBlo, off);
            }
        }
        __syncthreads();
        #pragma unroll
        for (int ks = 0; ks < 2; ks++) {
            const uint32_t kso = ks * 32;
            uint32_t af[4][4], bf[4][2];
            #pragma unroll
            for (int am = 0; am < 4; am++)
                ldsm4(af[am], sb + 0 * MAT_SM + a_off + kso + am * 16 * PITCH_B);
            #pragma unroll
            for (int an = 0; an < 4; an++)
                ldsm2(bf[an], sb + 2 * MAT_SM + b_off + kso + an * 8 * PITCH_B);
            #pragma unroll
            for (int am = 0; am < 4; am++)
                #pragma unroll
                for (int an = 0; an < 4; an++)
                    mma16816(acc[am][an], af[am], bf[an]);
            #pragma unroll
            for (int an = 0; an < 4; an++)
                ldsm2(bf[an], sb + 3 * MAT_SM + b_off + kso + an * 8 * PITCH_B);
            #pragma unroll
            for (int am = 0; am < 4; am++)
                #pragma unroll
                for (int an = 0; an < 4; an++)
                    mma16816(acc[am][an], af[am], bf[an]);
            #pragma unroll
            for (int am = 0; am < 4; am++)
                ldsm4(af[am], sb + 1 * MAT_SM + a_off + kso + am * 16 * PITCH_B);
            #pragma unroll
            for (int an = 0; an < 4; an++)
                ldsm2(bf[an], sb + 2 * MAT_SM + b_off + kso + an * 8 * PITCH_B);
            #pragma unroll
            for (int am = 0; am < 4; am++)
                #pragma unroll
                for (int an = 0; an < 4; an++)
                    mma16816(acc[am][an], af[am], bf[an]);
        }
        __syncthreads();
    }

    #pragma unroll
    for (int am = 0; am < 4; am++) {
        const int r0 = bm + wm * 64 + am * 16 + (lane >> 2);
        #pragma unroll
        for (int rr = 0; rr < 2; rr++) {
            const int r = r0 + rr * 8;
            float* crow = C + (size_t)r * N;
            const float* rrow = (MODE == 1) ? (resid + (size_t)r * N) : nullptr;
            #pragma unroll
            for (int an = 0; an < 4; an++) {
                const int col = bn + wn * 32 + an * 8 + 2 * (lane & 3);
                float v0 = acc[am][an][rr * 2 + 0];
                float v1 = acc[am][an][rr * 2 + 1];
                if (MODE != 0) { v0 += bias[col]; v1 += bias[col + 1]; }
                if (MODE == 2) {
                    v0 = 0.5f * v0 * (1.0f + erff(v0 * 0.70710678118654752f));
                    v1 = 0.5f * v1 * (1.0f + erff(v1 * 0.70710678118654752f));
                }
                if (MODE == 1) { v0 += rrow[col]; v1 += rrow[col + 1]; }
                *(float2*)(crow + col) = make_float2(v0, v1);
            }
        }
    }
}

// ---------------------------------------------------------------------------
// Tensor-core flash attention (FA2-style), single-pass bf16.
// Block: 256 threads = 8 warps, each warp owns 16 query rows (128-row Q tile).
// KV tiles of 64 keys. smem pitch 144B (conflict-free ldmatrix).
// grid: (SEQ/128, B*H, STAGES)
// ---------------------------------------------------------------------------
#define APITCH 144
__global__ void __launch_bounds__(256) attn_tc_kernel(
    const float* __restrict__ qkv, const float* __restrict__ focus_w,
    float* __restrict__ ocat)
{
    __shared__ __align__(16) char sm[(128 + 64 + 64) * APITCH];
    char* Qs = sm;
    char* Ks = sm + 128 * APITCH;
    char* Vs = Ks + 64 * APITCH;
    const uint32_t qsb = smem_u32(Qs);
    const uint32_t ksb = smem_u32(Ks);
    const uint32_t vsb = smem_u32(Vs);

    const int s  = blockIdx.z;
    const int b  = blockIdx.y / NH;
    const int hh = blockIdx.y % NH;
    const int t  = threadIdx.x;
    const int lane = t & 31, w = t >> 5;
    const int q0 = blockIdx.x * 128;

    // ---- load Q tile [128][64] f32 -> bf16 smem ----
    {
        const float* qptr = qkv + (size_t)(b * SEQ + q0) * CQKV + s * C3 + hh * HDIM;
        #pragma unroll
        for (int it = 0; it < 8; it++) {
            const int idx = t + it * 256;
            const int r = idx >> 4, c4 = idx & 15;
            float4 v = *(const float4*)(qptr + (size_t)r * CQKV + c4 * 4);
            *(uint2*)(Qs + r * APITCH + c4 * 8) =
                make_uint2(pack_bf16x2(v.x, v.y), pack_bf16x2(v.z, v.w));
        }
    }
    __syncthreads();
    uint32_t qf[4][4];
    #pragma unroll
    for (int kc = 0; kc < 4; kc++)
        ldsm4(qf[kc], qsb + (uint32_t)(w * 16 + (lane & 15)) * APITCH + kc * 32 + (lane >> 4) * 16);

    float of[8][4];
    #pragma unroll
    for (int dn = 0; dn < 8; dn++)
        #pragma unroll
        for (int q = 0; q < 4; q++) of[dn][q] = 0.0f;
    float m0 = -1e30f, m1 = -1e30f, l0 = 0.0f, l1 = 0.0f;
    const float scale = 0.125f;

    const float* kvbase = qkv + (size_t)b * SEQ * CQKV + s * C3 + CH + hh * HDIM;

    for (int kt = 0; kt < SEQ; kt += 64) {
        // ---- load K,V tiles [64][64] f32 -> bf16 smem ----
        __syncthreads();
        #pragma unroll
        for (int it = 0; it < 4; it++) {
            const int idx = t + it * 256;
            const int r = idx >> 4, c4 = idx & 15;
            const float* src = kvbase + (size_t)(kt + r) * CQKV + c4 * 4;
            float4 kv4 = *(const float4*)src;
            float4 vv4 = *(const float4*)(src + CH);
            *(uint2*)(Ks + r * APITCH + c4 * 8) =
                make_uint2(pack_bf16x2(kv4.x, kv4.y), pack_bf16x2(kv4.z, kv4.w));
            *(uint2*)(Vs + r * APITCH + c4 * 8) =
                make_uint2(pack_bf16x2(vv4.x, vv4.y), pack_bf16x2(vv4.z, vv4.w));
        }
        __syncthreads();

        // ---- S = Q @ K^T  (16 x 64 per warp) ----
        float sf[8][4];
        #pragma unroll
        for (int j = 0; j < 8; j++)
            #pragma unroll
            for (int q = 0; q < 4; q++) sf[j][q] = 0.0f;
        #pragma unroll
        for (int kc = 0; kc < 4; kc++) {
            #pragma unroll
            for (int np = 0; np < 4; np++) {
                uint32_t kb4[4];
                ldsm4(kb4, ksb + (uint32_t)(np * 16 + (lane & 7) + ((lane >> 4) << 3)) * APITCH
                              + kc * 32 + (((lane >> 3) & 1) << 4));
                mma16816(sf[2 * np],     qf[kc], kb4);
                mma16816(sf[2 * np + 1], qf[kc], kb4 + 2);
            }
        }

        // ---- online softmax ----
        float rmax0 = -1e30f, rmax1 = -1e30f;
        #pragma unroll
        for (int j = 0; j < 8; j++) {
            rmax0 = fmaxf(rmax0, fmaxf(sf[j][0], sf[j][1]));
            rmax1 = fmaxf(rmax1, fmaxf(sf[j][2], sf[j][3]));
        }
        rmax0 = fmaxf(rmax0, __shfl_xor_sync(0xffffffff, rmax0, 1));
        rmax0 = fmaxf(rmax0, __shfl_xor_sync(0xffffffff, rmax0, 2));
        rmax1 = fmaxf(rmax1, __shfl_xor_sync(0xffffffff, rmax1, 1));
        rmax1 = fmaxf(rmax1, __shfl_xor_sync(0xffffffff, rmax1, 2));
        const float mn0 = fmaxf(m0, rmax0 * scale);
        const float mn1 = fmaxf(m1, rmax1 * scale);
        const float a0 = __expf(m0 - mn0);
        const float a1 = __expf(m1 - mn1);
        float rs0 = 0.0f, rs1 = 0.0f;
        #pragma unroll
        for (int j = 0; j < 8; j++) {
            sf[j][0] = __expf(fmaf(sf[j][0], scale, -mn0));
            sf[j][1] = __expf(fmaf(sf[j][1], scale, -mn0));
            sf[j][2] = __expf(fmaf(sf[j][2], scale, -mn1));
            sf[j][3] = __expf(fmaf(sf[j][3], scale, -mn1));
            rs0 += sf[j][0] + sf[j][1];
            rs1 += sf[j][2] + sf[j][3];
        }
        rs0 += __shfl_xor_sync(0xffffffff, rs0, 1);
        rs0 += __shfl_xor_sync(0xffffffff, rs0, 2);
        rs1 += __shfl_xor_sync(0xffffffff, rs1, 1);
        rs1 += __shfl_xor_sync(0xffffffff, rs1, 2);
        l0 = l0 * a0 + rs0;
        l1 = l1 * a1 + rs1;
        m0 = mn0; m1 = mn1;
        #pragma unroll
        for (int dn = 0; dn < 8; dn++) {
            of[dn][0] *= a0; of[dn][1] *= a0;
            of[dn][2] *= a1; of[dn][3] *= a1;
        }

        // ---- O += P @ V ----
        #pragma unroll
        for (int kc = 0; kc < 4; kc++) {
            uint32_t pa[4];
            pa[0] = pack_bf16x2(sf[2 * kc][0],     sf[2 * kc][1]);
            pa[1] = pack_bf16x2(sf[2 * kc][2],     sf[2 * kc][3]);
            pa[2] = pack_bf16x2(sf[2 * kc + 1][0], sf[2 * kc + 1][1]);
            pa[3] = pack_bf16x2(sf[2 * kc + 1][2], sf[2 * kc + 1][3]);
            #pragma unroll
            for (int dp = 0; dp < 4; dp++) {
                uint32_t vb4[4];
                ldsm4t(vb4, vsb + (uint32_t)(kc * 16 + (lane & 15)) * APITCH
                               + dp * 32 + (lane >> 4) * 16);
                mma16816(of[2 * dp],     pa, vb4);
                mma16816(of[2 * dp + 1], pa, vb4 + 2);
            }
        }
    }

    // ---- write focus-scaled, normalized output ----
    const float f = focus_w[s];
    const float inv0 = f / l0, inv1 = f / l1;
    const int r0 = q0 + w * 16 + (lane >> 2);
    float* dst0 = ocat + (size_t)(b * SEQ + r0) * C3 + s * CH + hh * HDIM;
    float* dst1 = dst0 + (size_t)8 * C3;
    #pragma unroll
    for (int dn = 0; dn < 8; dn++) {
        const int col = dn * 8 + 2 * (lane & 3);
        *(float2*)(dst0 + col) = make_float2(of[dn][0] * inv0, of[dn][1] * inv0);
        *(float2*)(dst1 + col) = make_float2(of[dn][2] * inv1, of[dn][3] * inv1);
    }
}

// ---------------------------------------------------------------------------
// Launch
// ---------------------------------------------------------------------------
extern "C" void kernel_launch(void* const* d_in, const int* in_sizes, int n_in,
                              void* d_out, int out_size)
{
    const float* x      = (const float*)d_in[0];
    const float* qkv_w  = (const float*)d_in[1];
    const float* proj_w = (const float*)d_in[2];
    const float* proj_b = (const float*)d_in[3];
    const float* ln1_w  = (const float*)d_in[4];
    const float* ln1_b  = (const float*)d_in[5];
    const float* ln2_w  = (const float*)d_in[6];
    const float* ln2_b  = (const float*)d_in[7];
    const float* mlp_w1 = (const float*)d_in[8];
    const float* mlp_b1 = (const float*)d_in[9];
    const float* mlp_w2 = (const float*)d_in[10];
    const float* mlp_b2 = (const float*)d_in[11];
    const float* focus  = (const float*)d_in[12];
    float* out = (float*)d_out;

    float *h, *qkvb, *ocat, *x2, *mlp, *pw, *b2;
    cudaGetSymbolAddress((void**)&h,    g_h);
    cudaGetSymbolAddress((void**)&qkvb, g_qkv);
    cudaGetSymbolAddress((void**)&ocat, g_ocat);
    cudaGetSymbolAddress((void**)&x2,   g_x2);
    cudaGetSymbolAddress((void**)&mlp,  g_mlp);
    cudaGetSymbolAddress((void**)&pw,   g_projw);
    cudaGetSymbolAddress((void**)&b2,   g_bias2);

    // 1) h = LN1(x)
    ln_kernel<<<MROWS, 256>>>(x, ln1_w, ln1_b, h);
    // 2) pack proj weights/bias
    prepack_kernel<<<(CH * C3 + 255) / 256, 256>>>(proj_w, proj_b, focus);
    // 3) qkv = h @ qkv_w^T  (8192 x 6912 x 768)
    gemm_tc_kernel<0><<<dim3(CQKV / 128, MROWS / 128), 256>>>(
        h, qkv_w, nullptr, nullptr, qkvb, MROWS, CQKV, CH);
    // 4) attention (tensor-core flash)
    attn_tc_kernel<<<dim3(SEQ / 128, BB * NH, 3), 256>>>(qkvb, focus, ocat);
    // 5) x2 = x + ocat @ projw_cat^T + bias2  (8192 x 768 x 2304)
    gemm_tc_kernel<1><<<dim3(CH / 128, MROWS / 128), 256>>>(
        ocat, pw, b2, x, x2, MROWS, CH, C3);
    // 6) h = LN2(x2)
    ln_kernel<<<MROWS, 256>>>(x2, ln2_w, ln2_b, h);
    // 7) mlp = gelu(h @ mlp_w1^T + b1)  (8192 x 3072 x 768)
    gemm_tc_kernel<2><<<dim3(MLPH / 128, MROWS / 128), 256>>>(
        h, mlp_w1, mlp_b1, nullptr, mlp, MROWS, MLPH, CH);
    // 8) out = x2 + mlp @ mlp_w2^T + b2  (8192 x 768 x 3072)
    gemm_tc_kernel<1><<<dim3(CH / 128, MROWS / 128), 256>>>(
        mlp, mlp_w2, mlp_b2, x2, out, MROWS, CH, MLPH);
}

// round 5
// speedup vs baseline: 5.2765x; 1.4715x over previous
#include <cuda_runtime.h>
#include <cuda_bf16.h>
#include <math.h>
#include <stdint.h>

// Problem constants
#define BB    8
#define SEQ   1024
#define CH    768
#define NH    12
#define HDIM  64
#define MROWS (BB*SEQ)      // 8192 token rows
#define C3    (3*CH)        // 2304
#define CQKV  (3*C3)        // 6912
#define MLPH  (4*CH)        // 3072

// ---------------------------------------------------------------------------
// Scratch buffers
// ---------------------------------------------------------------------------
__device__ __nv_bfloat16 g_h16hi [(size_t)MROWS * CH];
__device__ __nv_bfloat16 g_h16lo [(size_t)MROWS * CH];
__device__ __nv_bfloat16 g_qkv16 [(size_t)MROWS * CQKV];
__device__ __nv_bfloat16 g_ocat16[(size_t)MROWS * C3];
__device__ __nv_bfloat16 g_mlp16hi[(size_t)MROWS * MLPH];
__device__ __nv_bfloat16 g_mlp16lo[(size_t)MROWS * MLPH];
__device__ float         g_x2   [(size_t)MROWS * CH];
__device__ __nv_bfloat16 g_wqkv16[(size_t)CQKV * CH];
__device__ __nv_bfloat16 g_wproj16[(size_t)CH * C3];
__device__ __nv_bfloat16 g_w1hi [(size_t)MLPH * CH];
__device__ __nv_bfloat16 g_w1lo [(size_t)MLPH * CH];
__device__ __nv_bfloat16 g_w2hi [(size_t)CH * MLPH];
__device__ __nv_bfloat16 g_w2lo [(size_t)CH * MLPH];
__device__ float         g_bias2[CH];

// ---------------------------------------------------------------------------
// PTX helpers (sm_80-level — compiles for plain sm_100)
// ---------------------------------------------------------------------------
__device__ __forceinline__ uint32_t smem_u32(const void* p) {
    uint32_t a;
    asm("{ .reg .u64 t; cvta.to.shared.u64 t, %1; cvt.u32.u64 %0, t; }" : "=r"(a) : "l"(p));
    return a;
}
__device__ __forceinline__ void ldsm4(uint32_t* r, uint32_t addr) {
    asm volatile("ldmatrix.sync.aligned.m8n8.x4.shared.b16 {%0,%1,%2,%3}, [%4];"
        : "=r"(r[0]), "=r"(r[1]), "=r"(r[2]), "=r"(r[3]) : "r"(addr));
}
__device__ __forceinline__ void ldsm4t(uint32_t* r, uint32_t addr) {
    asm volatile("ldmatrix.sync.aligned.m8n8.x4.trans.shared.b16 {%0,%1,%2,%3}, [%4];"
        : "=r"(r[0]), "=r"(r[1]), "=r"(r[2]), "=r"(r[3]) : "r"(addr));
}
__device__ __forceinline__ void ldsm2(uint32_t* r, uint32_t addr) {
    asm volatile("ldmatrix.sync.aligned.m8n8.x2.shared.b16 {%0,%1}, [%2];"
        : "=r"(r[0]), "=r"(r[1]) : "r"(addr));
}
__device__ __forceinline__ void mma16816(float* c, const uint32_t* a, const uint32_t* b) {
    asm volatile(
        "mma.sync.aligned.m16n8k16.row.col.f32.bf16.bf16.f32 "
        "{%0,%1,%2,%3}, {%4,%5,%6,%7}, {%8,%9}, {%0,%1,%2,%3};"
        : "+f"(c[0]), "+f"(c[1]), "+f"(c[2]), "+f"(c[3])
        : "r"(a[0]), "r"(a[1]), "r"(a[2]), "r"(a[3]), "r"(b[0]), "r"(b[1]));
}
__device__ __forceinline__ uint32_t pack_bf16x2(float lo, float hi) {
    __nv_bfloat162 p = __floats2bfloat162_rn(lo, hi);
    return *(uint32_t*)&p;
}
__device__ __forceinline__ void cp16(uint32_t saddr, const void* gptr) {
    asm volatile("cp.async.ca.shared.global [%0], [%1], 16;" :: "r"(saddr), "l"(gptr));
}
#define CP_COMMIT() asm volatile("cp.async.commit_group;")
#define CP_WAIT1()  asm volatile("cp.async.wait_group 1;")
#define CP_WAIT0()  asm volatile("cp.async.wait_group 0;")

__device__ __forceinline__ float gelu_f(float v) {
    return 0.5f * v * (1.0f + erff(v * 0.70710678118654752f));
}

// ---------------------------------------------------------------------------
// LayerNorm -> (hi, lo) bf16
// ---------------------------------------------------------------------------
__global__ void __launch_bounds__(256) ln_kernel(const float* __restrict__ x,
                                                 const float* __restrict__ w,
                                                 const float* __restrict__ b,
                                                 __nv_bfloat16* __restrict__ hhi,
                                                 __nv_bfloat16* __restrict__ hlo)
{
    __shared__ float red[2][8];
    const int row = blockIdx.x;
    const float* xr = x + (size_t)row * CH;
    const int t = threadIdx.x;
    float v0 = xr[t], v1 = xr[t + 256], v2 = xr[t + 512];
    float s  = v0 + v1 + v2;
    float sq = v0*v0 + v1*v1 + v2*v2;
    #pragma unroll
    for (int o = 16; o > 0; o >>= 1) {
        s  += __shfl_xor_sync(0xffffffff, s,  o);
        sq += __shfl_xor_sync(0xffffffff, sq, o);
    }
    const int warp = t >> 5, lane = t & 31;
    if (lane == 0) { red[0][warp] = s; red[1][warp] = sq; }
    __syncthreads();
    if (warp == 0) {
        s = red[0][lane & 7]; sq = red[1][lane & 7];
        #pragma unroll
        for (int o = 4; o > 0; o >>= 1) {
            s  += __shfl_xor_sync(0xffffffff, s,  o);
            sq += __shfl_xor_sync(0xffffffff, sq, o);
        }
        if (lane == 0) { red[0][0] = s; red[1][0] = sq; }
    }
    __syncthreads();
    const float mu  = red[0][0] * (1.0f / CH);
    float var = red[1][0] * (1.0f / CH) - mu * mu;
    var = fmaxf(var, 0.0f);
    const float inv = rsqrtf(var + 1e-5f);
    #pragma unroll
    for (int q = 0; q < 3; q++) {
        const int c = t + q * 256;
        const float v = (q == 0 ? v0 : q == 1 ? v1 : v2);
        const float val = (v - mu) * inv * w[c] + b[c];
        const __nv_bfloat16 hi = __float2bfloat16(val);
        hhi[(size_t)row * CH + c] = hi;
        hlo[(size_t)row * CH + c] = __float2bfloat16(val - __bfloat162float(hi));
    }
}

// ---------------------------------------------------------------------------
// Weight split-convert: hi (+ optional lo)
// ---------------------------------------------------------------------------
__global__ void __launch_bounds__(256) wsplit_kernel(const float* __restrict__ src,
                                                     __nv_bfloat16* __restrict__ hi,
                                                     __nv_bfloat16* __restrict__ lo,
                                                     int n)
{
    const int i = blockIdx.x * 256 + threadIdx.x;
    if (i < n) {
        const float v = src[i];
        const __nv_bfloat16 h = __float2bfloat16(v);
        hi[i] = h;
        if (lo) lo[i] = __float2bfloat16(v - __bfloat162float(h));
    }
}

// Prepack proj: wproj16[c][s*768+k] = bf16(proj_w[s][c][k]); bias2[c] = sum focus*proj_b
__global__ void __launch_bounds__(256) prepack_proj_kernel(const float* __restrict__ proj_w,
                                                           const float* __restrict__ proj_b,
                                                           const float* __restrict__ focus_w)
{
    const int idx = blockIdx.x * 256 + threadIdx.x;
    const int total = CH * C3;
    if (idx < total) {
        const int c   = idx / C3;
        const int rem = idx % C3;
        const int s   = rem / CH;
        const int k   = rem % CH;
        g_wproj16[idx] = __float2bfloat16(proj_w[((size_t)s * CH + c) * CH + k]);
    }
    if (idx < CH) {
        float acc = 0.0f;
        #pragma unroll
        for (int s = 0; s < 3; s++) acc += focus_w[s] * proj_b[s * CH + idx];
        g_bias2[idx] = acc;
    }
}

// ---------------------------------------------------------------------------
// bf16 tensor-core GEMM, cp.async double-buffered.
// C[m,n] = sum_k A[m,k]*B[n,k]; NSPLIT=1: Ahi*Bhi only. NSPLIT=3: +Ahi*Blo+Alo*Bhi
// MODE 0: plain -> bf16 out      MODE 1: +bias+resid -> f32 out
// MODE 2: gelu(.+bias) -> (hi,lo) bf16 out
// Tile 128x128, Kc=32, 256 threads = 8 warps (2m x 4n), warp tile 64x32.
// ---------------------------------------------------------------------------
#define PITCH_B 80
#define MAT_SM  (128 * PITCH_B)

template<int NSPLIT, int MODE>
__global__ void __launch_bounds__(256, 2) gemm16_kernel(
    const __nv_bfloat16* __restrict__ Ahi, const __nv_bfloat16* __restrict__ Alo,
    const __nv_bfloat16* __restrict__ Bhi, const __nv_bfloat16* __restrict__ Blo,
    const float* __restrict__ bias, const float* __restrict__ resid,
    void* __restrict__ Cout, void* __restrict__ Cout2, int M, int N, int K)
{
    constexpr int NMAT  = (NSPLIT == 1) ? 2 : 4;
    constexpr int STAGE = NMAT * MAT_SM;
    extern __shared__ __align__(16) char dynsm[];
    const uint32_t sb = smem_u32(dynsm);

    const int tid  = threadIdx.x;
    const int lane = tid & 31;
    const int wid  = tid >> 5;
    const int wm   = wid >> 2;
    const int wn   = wid & 3;
    const int bm = blockIdx.y * 128;
    const int bn = blockIdx.x * 128;

    const __nv_bfloat16* mbase[NMAT];
    mbase[0] = Ahi + (size_t)bm * K;
    mbase[1] = Bhi + (size_t)bn * K;
    if (NSPLIT == 3) {
        mbase[2] = Alo + (size_t)bm * K;
        mbase[3] = Blo + (size_t)bn * K;
    }

    float acc[4][4][4];
    #pragma unroll
    for (int i = 0; i < 4; i++)
        #pragma unroll
        for (int j = 0; j < 4; j++)
            #pragma unroll
            for (int q = 0; q < 4; q++) acc[i][j][q] = 0.0f;

    const uint32_t a_off = (uint32_t)(wm * 64 + (lane & 15)) * PITCH_B + (lane >> 4) * 16;
    const uint32_t b_off = (uint32_t)(wn * 32 + (lane & 7)) * PITCH_B + ((lane >> 3) & 1) * 16;

    const int nchunk = K >> 5;

    auto load_chunk = [&](int ic, int stg) {
        const int k0 = ic << 5;
        const uint32_t sbase = sb + stg * STAGE;
        #pragma unroll
        for (int it = 0; it < NMAT * 2; it++) {
            const int id = tid + it * 256;
            const int m  = id >> 9;
            const int rr = (id >> 2) & 127;
            const int c  = id & 3;
            cp16(sbase + m * MAT_SM + rr * PITCH_B + c * 16,
                 mbase[m] + (size_t)rr * K + k0 + c * 8);
        }
    };

    load_chunk(0, 0);
    CP_COMMIT();

    for (int ic = 0; ic < nchunk; ic++) {
        if (ic + 1 < nchunk) {
            load_chunk(ic + 1, (ic + 1) & 1);
            CP_COMMIT();
            CP_WAIT1();
        } else {
            CP_WAIT0();
        }
        __syncthreads();
        const uint32_t base = sb + (ic & 1) * STAGE;
        #pragma unroll
        for (int ks = 0; ks < 2; ks++) {
            const uint32_t kso = ks * 32;
            uint32_t af[4][4], bf[4][2];
            // pass 1: Ahi * Bhi
            #pragma unroll
            for (int am = 0; am < 4; am++)
                ldsm4(af[am], base + a_off + kso + am * 16 * PITCH_B);
            #pragma unroll
            for (int an = 0; an < 4; an++)
                ldsm2(bf[an], base + MAT_SM + b_off + kso + an * 8 * PITCH_B);
            #pragma unroll
            for (int am = 0; am < 4; am++)
                #pragma unroll
                for (int an = 0; an < 4; an++)
                    mma16816(acc[am][an], af[am], bf[an]);
            if (NSPLIT == 3) {
                // pass 2: Ahi * Blo
                #pragma unroll
                for (int an = 0; an < 4; an++)
                    ldsm2(bf[an], base + 3 * MAT_SM + b_off + kso + an * 8 * PITCH_B);
                #pragma unroll
                for (int am = 0; am < 4; am++)
                    #pragma unroll
                    for (int an = 0; an < 4; an++)
                        mma16816(acc[am][an], af[am], bf[an]);
                // pass 3: Alo * Bhi
                #pragma unroll
                for (int am = 0; am < 4; am++)
                    ldsm4(af[am], base + 2 * MAT_SM + a_off + kso + am * 16 * PITCH_B);
                #pragma unroll
                for (int an = 0; an < 4; an++)
                    ldsm2(bf[an], base + MAT_SM + b_off + kso + an * 8 * PITCH_B);
                #pragma unroll
                for (int am = 0; am < 4; am++)
                    #pragma unroll
                    for (int an = 0; an < 4; an++)
                        mma16816(acc[am][an], af[am], bf[an]);
            }
        }
        __syncthreads();
    }

    // ---- epilogue ----
    #pragma unroll
    for (int am = 0; am < 4; am++) {
        const int r0 = bm + wm * 64 + am * 16 + (lane >> 2);
        #pragma unroll
        for (int rr = 0; rr < 2; rr++) {
            const int r = r0 + rr * 8;
            #pragma unroll
            for (int an = 0; an < 4; an++) {
                const int col = bn + wn * 32 + an * 8 + 2 * (lane & 3);
                float v0 = acc[am][an][rr * 2 + 0];
                float v1 = acc[am][an][rr * 2 + 1];
                if (MODE == 0) {
                    *(uint32_t*)((__nv_bfloat16*)Cout + (size_t)r * N + col) =
                        pack_bf16x2(v0, v1);
                } else if (MODE == 1) {
                    v0 += bias[col] + resid[(size_t)r * N + col];
                    v1 += bias[col + 1] + resid[(size_t)r * N + col + 1];
                    *(float2*)((float*)Cout + (size_t)r * N + col) = make_float2(v0, v1);
                } else {
                    v0 = gelu_f(v0 + bias[col]);
                    v1 = gelu_f(v1 + bias[col + 1]);
                    const __nv_bfloat16 h0 = __float2bfloat16(v0);
                    const __nv_bfloat16 h1 = __float2bfloat16(v1);
                    *(uint32_t*)((__nv_bfloat16*)Cout + (size_t)r * N + col) =
                        pack_bf16x2(__bfloat162float(h0), __bfloat162float(h1));
                    *(uint32_t*)((__nv_bfloat16*)Cout2 + (size_t)r * N + col) =
                        pack_bf16x2(v0 - __bfloat162float(h0), v1 - __bfloat162float(h1));
                }
            }
        }
    }
}

// ---------------------------------------------------------------------------
// Tensor-core flash attention (bf16 in / bf16 out).
// 256 threads = 8 warps x 16 q-rows = 128-row Q tile; KV tiles of 64 keys.
// ---------------------------------------------------------------------------
#define APITCH 144
__global__ void __launch_bounds__(256) attn_tc_kernel(
    const __nv_bfloat16* __restrict__ qkv16, const float* __restrict__ focus_w,
    __nv_bfloat16* __restrict__ ocat16)
{
    __shared__ __align__(16) char sm[(128 + 64 + 64) * APITCH];
    char* Qs = sm;
    char* Ks = sm + 128 * APITCH;
    char* Vs = Ks + 64 * APITCH;
    const uint32_t qsb = smem_u32(Qs);
    const uint32_t ksb = smem_u32(Ks);
    const uint32_t vsb = smem_u32(Vs);

    const int s  = blockIdx.z;
    const int b  = blockIdx.y / NH;
    const int hh = blockIdx.y % NH;
    const int t  = threadIdx.x;
    const int lane = t & 31, w = t >> 5;
    const int q0 = blockIdx.x * 128;

    // ---- load Q tile [128][64] bf16 ----
    {
        const __nv_bfloat16* qptr = qkv16 + (size_t)(b * SEQ + q0) * CQKV + s * C3 + hh * HDIM;
        #pragma unroll
        for (int it = 0; it < 4; it++) {
            const int idx = t + it * 256;
            const int r = idx >> 3, c = idx & 7;
            *(uint4*)(Qs + r * APITCH + c * 16) =
                *(const uint4*)(qptr + (size_t)r * CQKV + c * 8);
        }
    }
    __syncthreads();
    uint32_t qf[4][4];
    #pragma unroll
    for (int kc = 0; kc < 4; kc++)
        ldsm4(qf[kc], qsb + (uint32_t)(w * 16 + (lane & 15)) * APITCH + kc * 32 + (lane >> 4) * 16);

    float of[8][4];
    #pragma unroll
    for (int dn = 0; dn < 8; dn++)
        #pragma unroll
        for (int q = 0; q < 4; q++) of[dn][q] = 0.0f;
    float m0 = -1e30f, m1 = -1e30f, l0 = 0.0f, l1 = 0.0f;
    const float scale = 0.125f;

    const __nv_bfloat16* kvb = qkv16 + (size_t)b * SEQ * CQKV + s * C3 + CH + hh * HDIM;

    for (int kt = 0; kt < SEQ; kt += 64) {
        __syncthreads();
        #pragma unroll
        for (int it = 0; it < 4; it++) {
            const int idx = t + it * 256;
            const int mm = idx >> 9;
            const int rr = (idx >> 3) & 63;
            const int c  = idx & 7;
            char* dst = (mm ? Vs : Ks);
            *(uint4*)(dst + rr * APITCH + c * 16) =
                *(const uint4*)(kvb + (size_t)(kt + rr) * CQKV + mm * CH + c * 8);
        }
        __syncthreads();

        // ---- S = Q @ K^T ----
        float sf[8][4];
        #pragma unroll
        for (int j = 0; j < 8; j++)
            #pragma unroll
            for (int q = 0; q < 4; q++) sf[j][q] = 0.0f;
        #pragma unroll
        for (int kc = 0; kc < 4; kc++) {
            #pragma unroll
            for (int np = 0; np < 4; np++) {
                uint32_t kb4[4];
                ldsm4(kb4, ksb + (uint32_t)(np * 16 + (lane & 7) + ((lane >> 4) << 3)) * APITCH
                              + kc * 32 + (((lane >> 3) & 1) << 4));
                mma16816(sf[2 * np],     qf[kc], kb4);
                mma16816(sf[2 * np + 1], qf[kc], kb4 + 2);
            }
        }

        // ---- online softmax ----
        float rmax0 = -1e30f, rmax1 = -1e30f;
        #pragma unroll
        for (int j = 0; j < 8; j++) {
            rmax0 = fmaxf(rmax0, fmaxf(sf[j][0], sf[j][1]));
            rmax1 = fmaxf(rmax1, fmaxf(sf[j][2], sf[j][3]));
        }
        rmax0 = fmaxf(rmax0, __shfl_xor_sync(0xffffffff, rmax0, 1));
        rmax0 = fmaxf(rmax0, __shfl_xor_sync(0xffffffff, rmax0, 2));
        rmax1 = fmaxf(rmax1, __shfl_xor_sync(0xffffffff, rmax1, 1));
        rmax1 = fmaxf(rmax1, __shfl_xor_sync(0xffffffff, rmax1, 2));
        const float mn0 = fmaxf(m0, rmax0 * scale);
        const float mn1 = fmaxf(m1, rmax1 * scale);
        const float a0 = __expf(m0 - mn0);
        const float a1 = __expf(m1 - mn1);
        float rs0 = 0.0f, rs1 = 0.0f;
        #pragma unroll
        for (int j = 0; j < 8; j++) {
            sf[j][0] = __expf(fmaf(sf[j][0], scale, -mn0));
            sf[j][1] = __expf(fmaf(sf[j][1], scale, -mn0));
            sf[j][2] = __expf(fmaf(sf[j][2], scale, -mn1));
            sf[j][3] = __expf(fmaf(sf[j][3], scale, -mn1));
            rs0 += sf[j][0] + sf[j][1];
            rs1 += sf[j][2] + sf[j][3];
        }
        rs0 += __shfl_xor_sync(0xffffffff, rs0, 1);
        rs0 += __shfl_xor_sync(0xffffffff, rs0, 2);
        rs1 += __shfl_xor_sync(0xffffffff, rs1, 1);
        rs1 += __shfl_xor_sync(0xffffffff, rs1, 2);
        l0 = l0 * a0 + rs0;
        l1 = l1 * a1 + rs1;
        m0 = mn0; m1 = mn1;
        #pragma unroll
        for (int dn = 0; dn < 8; dn++) {
            of[dn][0] *= a0; of[dn][1] *= a0;
            of[dn][2] *= a1; of[dn][3] *= a1;
        }

        // ---- O += P @ V ----
        #pragma unroll
        for (int kc = 0; kc < 4; kc++) {
            uint32_t pa[4];
            pa[0] = pack_bf16x2(sf[2 * kc][0],     sf[2 * kc][1]);
            pa[1] = pack_bf16x2(sf[2 * kc][2],     sf[2 * kc][3]);
            pa[2] = pack_bf16x2(sf[2 * kc + 1][0], sf[2 * kc + 1][1]);
            pa[3] = pack_bf16x2(sf[2 * kc + 1][2], sf[2 * kc + 1][3]);
            #pragma unroll
            for (int dp = 0; dp < 4; dp++) {
                uint32_t vb4[4];
                ldsm4t(vb4, vsb + (uint32_t)(kc * 16 + (lane & 15)) * APITCH
                               + dp * 32 + (lane >> 4) * 16);
                mma16816(of[2 * dp],     pa, vb4);
                mma16816(of[2 * dp + 1], pa, vb4 + 2);
            }
        }
    }

    // ---- write focus-scaled, normalized bf16 output ----
    const float f = focus_w[s];
    const float inv0 = f / l0, inv1 = f / l1;
    const int r0 = q0 + w * 16 + (lane >> 2);
    __nv_bfloat16* dst0 = ocat16 + (size_t)(b * SEQ + r0) * C3 + s * CH + hh * HDIM;
    __nv_bfloat16* dst1 = dst0 + (size_t)8 * C3;
    #pragma unroll
    for (int dn = 0; dn < 8; dn++) {
        const int col = dn * 8 + 2 * (lane & 3);
        *(uint32_t*)(dst0 + col) = pack_bf16x2(of[dn][0] * inv0, of[dn][1] * inv0);
        *(uint32_t*)(dst1 + col) = pack_bf16x2(of[dn][2] * inv1, of[dn][3] * inv1);
    }
}

// ---------------------------------------------------------------------------
// Launch
// ---------------------------------------------------------------------------
extern "C" void kernel_launch(void* const* d_in, const int* in_sizes, int n_in,
                              void* d_out, int out_size)
{
    const float* x      = (const float*)d_in[0];
    const float* qkv_w  = (const float*)d_in[1];
    const float* proj_w = (const float*)d_in[2];
    const float* proj_b = (const float*)d_in[3];
    const float* ln1_w  = (const float*)d_in[4];
    const float* ln1_b  = (const float*)d_in[5];
    const float* ln2_w  = (const float*)d_in[6];
    const float* ln2_b  = (const float*)d_in[7];
    const float* mlp_w1 = (const float*)d_in[8];
    const float* mlp_b1 = (const float*)d_in[9];
    const float* mlp_w2 = (const float*)d_in[10];
    const float* mlp_b2 = (const float*)d_in[11];
    const float* focus  = (const float*)d_in[12];
    float* out = (float*)d_out;

    __nv_bfloat16 *hhi, *hlo, *qkv16, *ocat16, *mhi, *mlo;
    __nv_bfloat16 *wqkv, *wproj, *w1hi, *w1lo, *w2hi, *w2lo;
    float *x2, *b2;
    cudaGetSymbolAddress((void**)&hhi,   g_h16hi);
    cudaGetSymbolAddress((void**)&hlo,   g_h16lo);
    cudaGetSymbolAddress((void**)&qkv16, g_qkv16);
    cudaGetSymbolAddress((void**)&ocat16,g_ocat16);
    cudaGetSymbolAddress((void**)&mhi,   g_mlp16hi);
    cudaGetSymbolAddress((void**)&mlo,   g_mlp16lo);
    cudaGetSymbolAddress((void**)&x2,    g_x2);
    cudaGetSymbolAddress((void**)&wqkv,  g_wqkv16);
    cudaGetSymbolAddress((void**)&wproj, g_wproj16);
    cudaGetSymbolAddress((void**)&w1hi,  g_w1hi);
    cudaGetSymbolAddress((void**)&w1lo,  g_w1lo);
    cudaGetSymbolAddress((void**)&w2hi,  g_w2hi);
    cudaGetSymbolAddress((void**)&w2lo,  g_w2lo);
    cudaGetSymbolAddress((void**)&b2,    g_bias2);

    const int SM1 = 2 * 2 * MAT_SM;   // 40960 (NSPLIT=1, 2 stages)
    const int SM3 = 2 * 4 * MAT_SM;   // 81920 (NSPLIT=3, 2 stages)
    cudaFuncSetAttribute(gemm16_kernel<1,0>, cudaFuncAttributeMaxDynamicSharedMemorySize, SM1);
    cudaFuncSetAttribute(gemm16_kernel<1,1>, cudaFuncAttributeMaxDynamicSharedMemorySize, SM1);
    cudaFuncSetAttribute(gemm16_kernel<3,2>, cudaFuncAttributeMaxDynamicSharedMemorySize, SM3);
    cudaFuncSetAttribute(gemm16_kernel<3,1>, cudaFuncAttributeMaxDynamicSharedMemorySize, SM3);

    // --- prepack weights (bf16 / split) ---
    wsplit_kernel<<<(CQKV * CH + 255) / 256, 256>>>(qkv_w, wqkv, nullptr, CQKV * CH);
    prepack_proj_kernel<<<(CH * C3 + 255) / 256, 256>>>(proj_w, proj_b, focus);
    wsplit_kernel<<<(MLPH * CH + 255) / 256, 256>>>(mlp_w1, w1hi, w1lo, MLPH * CH);
    wsplit_kernel<<<(CH * MLPH + 255) / 256, 256>>>(mlp_w2, w2hi, w2lo, CH * MLPH);

    // 1) h = LN1(x) -> bf16 hi/lo
    ln_kernel<<<MROWS, 256>>>(x, ln1_w, ln1_b, hhi, hlo);
    // 2) qkv16 = h @ qkv_w^T  (single-pass bf16, bf16 out)
    gemm16_kernel<1,0><<<dim3(CQKV / 128, MROWS / 128), 256, SM1>>>(
        hhi, nullptr, wqkv, nullptr, nullptr, nullptr, qkv16, nullptr, MROWS, CQKV, CH);
    // 3) attention (bf16 in/out, focus-scaled)
    attn_tc_kernel<<<dim3(SEQ / 128, BB * NH, 3), 256>>>(qkv16, focus, ocat16);
    // 4) x2 = x + ocat @ projw^T + bias2  (single-pass bf16, f32 out)
    gemm16_kernel<1,1><<<dim3(CH / 128, MROWS / 128), 256, SM1>>>(
        ocat16, nullptr, wproj, nullptr, b2, x, x2, nullptr, MROWS, CH, C3);
    // 5) h2 = LN2(x2) -> bf16 hi/lo
    ln_kernel<<<MROWS, 256>>>(x2, ln2_w, ln2_b, hhi, hlo);
    // 6) mlp = gelu(h2 @ w1^T + b1)  (split 3-pass, hi/lo bf16 out)
    gemm16_kernel<3,2><<<dim3(MLPH / 128, MROWS / 128), 256, SM3>>>(
        hhi, hlo, w1hi, w1lo, mlp_b1, nullptr, mhi, mlo, MROWS, MLPH, CH);
    // 7) out = x2 + mlp @ w2^T + b2  (split 3-pass, f32 out)
    gemm16_kernel<3,1><<<dim3(CH / 128, MROWS / 128), 256, SM3>>>(
        mhi, mlo, w2hi, w2lo, mlp_b2, x2, out, nullptr, MROWS, CH, MLPH);
}

// round 6
// speedup vs baseline: 7.0709x; 1.3401x over previous
#include <cuda_runtime.h>
#include <cuda_fp16.h>
#include <math.h>
#include <stdint.h>

// Problem constants
#define BB    8
#define SEQ   1024
#define CH    768
#define NH    12
#define HDIM  64
#define MROWS (BB*SEQ)      // 8192 token rows
#define C3    (3*CH)        // 2304
#define CQKV  (3*C3)        // 6912
#define MLPH  (4*CH)        // 3072

// ---------------------------------------------------------------------------
// Scratch buffers (all fp16 activations; fp32 residual trunk)
// ---------------------------------------------------------------------------
__device__ __half g_h16   [(size_t)MROWS * CH];
__device__ __half g_qkv16 [(size_t)MROWS * CQKV];
__device__ __half g_ocat16[(size_t)MROWS * C3];
__device__ __half g_mlp16 [(size_t)MROWS * MLPH];
__device__ float  g_x2    [(size_t)MROWS * CH];
__device__ __half g_wqkv16[(size_t)CQKV * CH];
__device__ __half g_wproj16[(size_t)CH * C3];
__device__ __half g_w116  [(size_t)MLPH * CH];
__device__ __half g_w216  [(size_t)CH * MLPH];
__device__ float  g_bias2 [CH];

// ---------------------------------------------------------------------------
// PTX helpers (sm_80-level — compiles for plain sm_100)
// ---------------------------------------------------------------------------
__device__ __forceinline__ uint32_t smem_u32(const void* p) {
    uint32_t a;
    asm("{ .reg .u64 t; cvta.to.shared.u64 t, %1; cvt.u32.u64 %0, t; }" : "=r"(a) : "l"(p));
    return a;
}
__device__ __forceinline__ void ldsm4(uint32_t* r, uint32_t addr) {
    asm volatile("ldmatrix.sync.aligned.m8n8.x4.shared.b16 {%0,%1,%2,%3}, [%4];"
        : "=r"(r[0]), "=r"(r[1]), "=r"(r[2]), "=r"(r[3]) : "r"(addr));
}
__device__ __forceinline__ void ldsm4t(uint32_t* r, uint32_t addr) {
    asm volatile("ldmatrix.sync.aligned.m8n8.x4.trans.shared.b16 {%0,%1,%2,%3}, [%4];"
        : "=r"(r[0]), "=r"(r[1]), "=r"(r[2]), "=r"(r[3]) : "r"(addr));
}
__device__ __forceinline__ void ldsm2(uint32_t* r, uint32_t addr) {
    asm volatile("ldmatrix.sync.aligned.m8n8.x2.shared.b16 {%0,%1}, [%2];"
        : "=r"(r[0]), "=r"(r[1]) : "r"(addr));
}
// fp16 inputs, fp32 accumulate
__device__ __forceinline__ void mma16816(float* c, const uint32_t* a, const uint32_t* b) {
    asm volatile(
        "mma.sync.aligned.m16n8k16.row.col.f32.f16.f16.f32 "
        "{%0,%1,%2,%3}, {%4,%5,%6,%7}, {%8,%9}, {%0,%1,%2,%3};"
        : "+f"(c[0]), "+f"(c[1]), "+f"(c[2]), "+f"(c[3])
        : "r"(a[0]), "r"(a[1]), "r"(a[2]), "r"(a[3]), "r"(b[0]), "r"(b[1]));
}
__device__ __forceinline__ uint32_t pack_h2(float lo, float hi) {
    __half2 p = __floats2half2_rn(lo, hi);
    return *(uint32_t*)&p;
}
__device__ __forceinline__ void cp16(uint32_t saddr, const void* gptr) {
    asm volatile("cp.async.ca.shared.global [%0], [%1], 16;" :: "r"(saddr), "l"(gptr));
}
#define CP_COMMIT() asm volatile("cp.async.commit_group;")
#define CP_WAIT2()  asm volatile("cp.async.wait_group 2;")
#define CP_WAIT1()  asm volatile("cp.async.wait_group 1;")
#define CP_WAIT0()  asm volatile("cp.async.wait_group 0;")

__device__ __forceinline__ float gelu_f(float v) {
    return 0.5f * v * (1.0f + erff(v * 0.70710678118654752f));
}

// ---------------------------------------------------------------------------
// LayerNorm -> fp16
// ---------------------------------------------------------------------------
__global__ void __launch_bounds__(256) ln_kernel(const float* __restrict__ x,
                                                 const float* __restrict__ w,
                                                 const float* __restrict__ b,
                                                 __half* __restrict__ hout)
{
    __shared__ float red[2][8];
    const int row = blockIdx.x;
    const float* xr = x + (size_t)row * CH;
    const int t = threadIdx.x;
    float v0 = xr[t], v1 = xr[t + 256], v2 = xr[t + 512];
    float s  = v0 + v1 + v2;
    float sq = v0*v0 + v1*v1 + v2*v2;
    #pragma unroll
    for (int o = 16; o > 0; o >>= 1) {
        s  += __shfl_xor_sync(0xffffffff, s,  o);
        sq += __shfl_xor_sync(0xffffffff, sq, o);
    }
    const int warp = t >> 5, lane = t & 31;
    if (lane == 0) { red[0][warp] = s; red[1][warp] = sq; }
    __syncthreads();
    if (warp == 0) {
        s = red[0][lane & 7]; sq = red[1][lane & 7];
        #pragma unroll
        for (int o = 4; o > 0; o >>= 1) {
            s  += __shfl_xor_sync(0xffffffff, s,  o);
            sq += __shfl_xor_sync(0xffffffff, sq, o);
        }
        if (lane == 0) { red[0][0] = s; red[1][0] = sq; }
    }
    __syncthreads();
    const float mu  = red[0][0] * (1.0f / CH);
    float var = red[1][0] * (1.0f / CH) - mu * mu;
    var = fmaxf(var, 0.0f);
    const float inv = rsqrtf(var + 1e-5f);
    __half* orow = hout + (size_t)row * CH;
    orow[t]       = __float2half_rn((v0 - mu) * inv * w[t]       + b[t]);
    orow[t + 256] = __float2half_rn((v1 - mu) * inv * w[t + 256] + b[t + 256]);
    orow[t + 512] = __float2half_rn((v2 - mu) * inv * w[t + 512] + b[t + 512]);
}

// ---------------------------------------------------------------------------
// Weight convert fp32 -> fp16 (vectorized: 4 elems/thread)
// ---------------------------------------------------------------------------
__global__ void __launch_bounds__(256) wconv_kernel(const float* __restrict__ src,
                                                    __half* __restrict__ dst, int n4)
{
    const int i = blockIdx.x * 256 + threadIdx.x;
    if (i < n4) {
        float4 v = *(const float4*)(src + (size_t)i * 4);
        *(uint2*)(dst + (size_t)i * 4) = make_uint2(pack_h2(v.x, v.y), pack_h2(v.z, v.w));
    }
}

// Prepack proj: wproj16[c][s*768+k] = fp16(proj_w[s][c][k]); bias2[c] = sum focus*proj_b
__global__ void __launch_bounds__(256) prepack_proj_kernel(const float* __restrict__ proj_w,
                                                           const float* __restrict__ proj_b,
                                                           const float* __restrict__ focus_w)
{
    const int idx = blockIdx.x * 256 + threadIdx.x;
    const int total = CH * C3;
    if (idx < total) {
        const int c   = idx / C3;
        const int rem = idx % C3;
        const int s   = rem / CH;
        const int k   = rem % CH;
        g_wproj16[idx] = __float2half_rn(proj_w[((size_t)s * CH + c) * CH + k]);
    }
    if (idx < CH) {
        float acc = 0.0f;
        #pragma unroll
        for (int s = 0; s < 3; s++) acc += focus_w[s] * proj_b[s * CH + idx];
        g_bias2[idx] = acc;
    }
}

// ---------------------------------------------------------------------------
// fp16 tensor-core GEMM, 4-stage cp.async pipeline.
// C[m,n] = sum_k A[m,k]*B[n,k]  (A: MxK row-major, B: NxK row-major)
// MODE 0: plain -> fp16 out    MODE 1: +bias+resid -> f32 out
// MODE 2: gelu(.+bias) -> fp16 out
// Tile 128x128, Kc=32, 256 threads = 8 warps (2m x 4n), warp tile 64x32.
// ---------------------------------------------------------------------------
#define PITCH_B 80
#define MAT_SM  (128 * PITCH_B)
#define STAGE_B (2 * MAT_SM)
#define NSTAGE  4
#define GSMEM   (NSTAGE * STAGE_B)   // 81920

template<int MODE>
__global__ void __launch_bounds__(256, 2) gemm16_kernel(
    const __half* __restrict__ A, const __half* __restrict__ B,
    const float* __restrict__ bias, const float* __restrict__ resid,
    void* __restrict__ Cout, int M, int N, int K)
{
    extern __shared__ __align__(16) char dynsm[];
    const uint32_t sb = smem_u32(dynsm);

    const int tid  = threadIdx.x;
    const int lane = tid & 31;
    const int wid  = tid >> 5;
    const int wm   = wid >> 2;
    const int wn   = wid & 3;
    const int bm = blockIdx.y * 128;
    const int bn = blockIdx.x * 128;

    const __half* Abase = A + (size_t)bm * K;
    const __half* Bbase = B + (size_t)bn * K;

    float acc[4][4][4];
    #pragma unroll
    for (int i = 0; i < 4; i++)
        #pragma unroll
        for (int j = 0; j < 4; j++)
            #pragma unroll
            for (int q = 0; q < 4; q++) acc[i][j][q] = 0.0f;

    const uint32_t a_off = (uint32_t)(wm * 64 + (lane & 15)) * PITCH_B + (lane >> 4) * 16;
    const uint32_t b_off = (uint32_t)(wn * 32 + (lane & 7)) * PITCH_B + ((lane >> 3) & 1) * 16;

    const int nchunk = K >> 5;

    auto load_chunk = [&](int ic, int stg) {
        const int k0 = ic << 5;
        const uint32_t sbase = sb + stg * STAGE_B;
        #pragma unroll
        for (int it = 0; it < 4; it++) {
            const int id = tid + it * 256;
            const int m  = id >> 9;           // 0: A, 1: B
            const int rr = (id >> 2) & 127;
            const int c  = id & 3;
            cp16(sbase + m * MAT_SM + rr * PITCH_B + c * 16,
                 (m ? Bbase : Abase) + (size_t)rr * K + k0 + c * 8);
        }
    };

    // prologue: fill NSTAGE-1 stages (nchunk >= 24 always here)
    #pragma unroll
    for (int i = 0; i < NSTAGE - 1; i++) { load_chunk(i, i); CP_COMMIT(); }

    for (int ic = 0; ic < nchunk; ic++) {
        const int rem = nchunk - 1 - ic;
        if (rem >= 2) CP_WAIT2(); else if (rem == 1) CP_WAIT1(); else CP_WAIT0();
        __syncthreads();
        if (ic + NSTAGE - 1 < nchunk) {
            load_chunk(ic + NSTAGE - 1, (ic + NSTAGE - 1) & (NSTAGE - 1));
            CP_COMMIT();
        }
        const uint32_t base = sb + (ic & (NSTAGE - 1)) * STAGE_B;
        #pragma unroll
        for (int ks = 0; ks < 2; ks++) {
            const uint32_t kso = ks * 32;
            uint32_t af[4][4], bf[4][2];
            #pragma unroll
            for (int am = 0; am < 4; am++)
                ldsm4(af[am], base + a_off + kso + am * 16 * PITCH_B);
            #pragma unroll
            for (int an = 0; an < 4; an++)
                ldsm2(bf[an], base + MAT_SM + b_off + kso + an * 8 * PITCH_B);
            #pragma unroll
            for (int am = 0; am < 4; am++)
                #pragma unroll
                for (int an = 0; an < 4; an++)
                    mma16816(acc[am][an], af[am], bf[an]);
        }
        __syncthreads();
    }

    // ---- epilogue ----
    #pragma unroll
    for (int am = 0; am < 4; am++) {
        const int r0 = bm + wm * 64 + am * 16 + (lane >> 2);
        #pragma unroll
        for (int rr = 0; rr < 2; rr++) {
            const int r = r0 + rr * 8;
            #pragma unroll
            for (int an = 0; an < 4; an++) {
                const int col = bn + wn * 32 + an * 8 + 2 * (lane & 3);
                float v0 = acc[am][an][rr * 2 + 0];
                float v1 = acc[am][an][rr * 2 + 1];
                if (MODE == 0) {
                    *(uint32_t*)((__half*)Cout + (size_t)r * N + col) = pack_h2(v0, v1);
                } else if (MODE == 1) {
                    v0 += bias[col] + resid[(size_t)r * N + col];
                    v1 += bias[col + 1] + resid[(size_t)r * N + col + 1];
                    *(float2*)((float*)Cout + (size_t)r * N + col) = make_float2(v0, v1);
                } else {
                    v0 = gelu_f(v0 + bias[col]);
                    v1 = gelu_f(v1 + bias[col + 1]);
                    *(uint32_t*)((__half*)Cout + (size_t)r * N + col) = pack_h2(v0, v1);
                }
            }
        }
    }
}

// ---------------------------------------------------------------------------
// Tensor-core flash attention (fp16 in / fp16 out).
// 256 threads = 8 warps x 16 q-rows = 128-row Q tile; KV tiles of 64 keys.
// ---------------------------------------------------------------------------
#define APITCH 144
__global__ void __launch_bounds__(256) attn_tc_kernel(
    const __half* __restrict__ qkv16, const float* __restrict__ focus_w,
    __half* __restrict__ ocat16)
{
    __shared__ __align__(16) char sm[(128 + 64 + 64) * APITCH];
    char* Qs = sm;
    char* Ks = sm + 128 * APITCH;
    char* Vs = Ks + 64 * APITCH;
    const uint32_t qsb = smem_u32(Qs);
    const uint32_t ksb = smem_u32(Ks);
    const uint32_t vsb = smem_u32(Vs);

    const int s  = blockIdx.z;
    const int b  = blockIdx.y / NH;
    const int hh = blockIdx.y % NH;
    const int t  = threadIdx.x;
    const int lane = t & 31, w = t >> 5;
    const int q0 = blockIdx.x * 128;

    // ---- load Q tile [128][64] fp16 ----
    {
        const __half* qptr = qkv16 + (size_t)(b * SEQ + q0) * CQKV + s * C3 + hh * HDIM;
        #pragma unroll
        for (int it = 0; it < 4; it++) {
            const int idx = t + it * 256;
            const int r = idx >> 3, c = idx & 7;
            *(uint4*)(Qs + r * APITCH + c * 16) =
                *(const uint4*)(qptr + (size_t)r * CQKV + c * 8);
        }
    }
    __syncthreads();
    uint32_t qf[4][4];
    #pragma unroll
    for (int kc = 0; kc < 4; kc++)
        ldsm4(qf[kc], qsb + (uint32_t)(w * 16 + (lane & 15)) * APITCH + kc * 32 + (lane >> 4) * 16);

    float of[8][4];
    #pragma unroll
    for (int dn = 0; dn < 8; dn++)
        #pragma unroll
        for (int q = 0; q < 4; q++) of[dn][q] = 0.0f;
    float m0 = -1e30f, m1 = -1e30f, l0 = 0.0f, l1 = 0.0f;
    const float scale = 0.125f;

    const __half* kvb = qkv16 + (size_t)b * SEQ * CQKV + s * C3 + CH + hh * HDIM;

    for (int kt = 0; kt < SEQ; kt += 64) {
        __syncthreads();
        #pragma unroll
        for (int it = 0; it < 4; it++) {
            const int idx = t + it * 256;
            const int mm = idx >> 9;
            const int rr = (idx >> 3) & 63;
            const int c  = idx & 7;
            char* dst = (mm ? Vs : Ks);
            *(uint4*)(dst + rr * APITCH + c * 16) =
                *(const uint4*)(kvb + (size_t)(kt + rr) * CQKV + mm * CH + c * 8);
        }
        __syncthreads();

        // ---- S = Q @ K^T ----
        float sf[8][4];
        #pragma unroll
        for (int j = 0; j < 8; j++)
            #pragma unroll
            for (int q = 0; q < 4; q++) sf[j][q] = 0.0f;
        #pragma unroll
        for (int kc = 0; kc < 4; kc++) {
            #pragma unroll
            for (int np = 0; np < 4; np++) {
                uint32_t kb4[4];
                ldsm4(kb4, ksb + (uint32_t)(np * 16 + (lane & 7) + ((lane >> 4) << 3)) * APITCH
                              + kc * 32 + (((lane >> 3) & 1) << 4));
                mma16816(sf[2 * np],     qf[kc], kb4);
                mma16816(sf[2 * np + 1], qf[kc], kb4 + 2);
            }
        }

        // ---- online softmax ----
        float rmax0 = -1e30f, rmax1 = -1e30f;
        #pragma unroll
        for (int j = 0; j < 8; j++) {
            rmax0 = fmaxf(rmax0, fmaxf(sf[j][0], sf[j][1]));
            rmax1 = fmaxf(rmax1, fmaxf(sf[j][2], sf[j][3]));
        }
        rmax0 = fmaxf(rmax0, __shfl_xor_sync(0xffffffff, rmax0, 1));
        rmax0 = fmaxf(rmax0, __shfl_xor_sync(0xffffffff, rmax0, 2));
        rmax1 = fmaxf(rmax1, __shfl_xor_sync(0xffffffff, rmax1, 1));
        rmax1 = fmaxf(rmax1, __shfl_xor_sync(0xffffffff, rmax1, 2));
        const float mn0 = fmaxf(m0, rmax0 * scale);
        const float mn1 = fmaxf(m1, rmax1 * scale);
        const float a0 = __expf(m0 - mn0);
        const float a1 = __expf(m1 - mn1);
        float rs0 = 0.0f, rs1 = 0.0f;
        #pragma unroll
        for (int j = 0; j < 8; j++) {
            sf[j][0] = __expf(fmaf(sf[j][0], scale, -mn0));
            sf[j][1] = __expf(fmaf(sf[j][1], scale, -mn0));
            sf[j][2] = __expf(fmaf(sf[j][2], scale, -mn1));
            sf[j][3] = __expf(fmaf(sf[j][3], scale, -mn1));
            rs0 += sf[j][0] + sf[j][1];
            rs1 += sf[j][2] + sf[j][3];
        }
        rs0 += __shfl_xor_sync(0xffffffff, rs0, 1);
        rs0 += __shfl_xor_sync(0xffffffff, rs0, 2);
        rs1 += __shfl_xor_sync(0xffffffff, rs1, 1);
        rs1 += __shfl_xor_sync(0xffffffff, rs1, 2);
        l0 = l0 * a0 + rs0;
        l1 = l1 * a1 + rs1;
        m0 = mn0; m1 = mn1;
        #pragma unroll
        for (int dn = 0; dn < 8; dn++) {
            of[dn][0] *= a0; of[dn][1] *= a0;
            of[dn][2] *= a1; of[dn][3] *= a1;
        }

        // ---- O += P @ V ----
        #pragma unroll
        for (int kc = 0; kc < 4; kc++) {
            uint32_t pa[4];
            pa[0] = pack_h2(sf[2 * kc][0],     sf[2 * kc][1]);
            pa[1] = pack_h2(sf[2 * kc][2],     sf[2 * kc][3]);
            pa[2] = pack_h2(sf[2 * kc + 1][0], sf[2 * kc + 1][1]);
            pa[3] = pack_h2(sf[2 * kc + 1][2], sf[2 * kc + 1][3]);
            #pragma unroll
            for (int dp = 0; dp < 4; dp++) {
                uint32_t vb4[4];
                ldsm4t(vb4, vsb + (uint32_t)(kc * 16 + (lane & 15)) * APITCH
                               + dp * 32 + (lane >> 4) * 16);
                mma16816(of[2 * dp],     pa, vb4);
                mma16816(of[2 * dp + 1], pa, vb4 + 2);
            }
        }
    }

    // ---- write focus-scaled, normalized fp16 output ----
    const float f = focus_w[s];
    const float inv0 = f / l0, inv1 = f / l1;
    const int r0 = q0 + w * 16 + (lane >> 2);
    __half* dst0 = ocat16 + (size_t)(b * SEQ + r0) * C3 + s * CH + hh * HDIM;
    __half* dst1 = dst0 + (size_t)8 * C3;
    #pragma unroll
    for (int dn = 0; dn < 8; dn++) {
        const int col = dn * 8 + 2 * (lane & 3);
        *(uint32_t*)(dst0 + col) = pack_h2(of[dn][0] * inv0, of[dn][1] * inv0);
        *(uint32_t*)(dst1 + col) = pack_h2(of[dn][2] * inv1, of[dn][3] * inv1);
    }
}

// ---------------------------------------------------------------------------
// Launch
// ---------------------------------------------------------------------------
extern "C" void kernel_launch(void* const* d_in, const int* in_sizes, int n_in,
                              void* d_out, int out_size)
{
    const float* x      = (const float*)d_in[0];
    const float* qkv_w  = (const float*)d_in[1];
    const float* proj_w = (const float*)d_in[2];
    const float* proj_b = (const float*)d_in[3];
    const float* ln1_w  = (const float*)d_in[4];
    const float* ln1_b  = (const float*)d_in[5];
    const float* ln2_w  = (const float*)d_in[6];
    const float* ln2_b  = (const float*)d_in[7];
    const float* mlp_w1 = (const float*)d_in[8];
    const float* mlp_b1 = (const float*)d_in[9];
    const float* mlp_w2 = (const float*)d_in[10];
    const float* mlp_b2 = (const float*)d_in[11];
    const float* focus  = (const float*)d_in[12];
    float* out = (float*)d_out;

    __half *h16, *qkv16, *ocat16, *mlp16, *wqkv, *wproj, *w1, *w2;
    float *x2, *b2;
    cudaGetSymbolAddress((void**)&h16,   g_h16);
    cudaGetSymbolAddress((void**)&qkv16, g_qkv16);
    cudaGetSymbolAddress((void**)&ocat16,g_ocat16);
    cudaGetSymbolAddress((void**)&mlp16, g_mlp16);
    cudaGetSymbolAddress((void**)&x2,    g_x2);
    cudaGetSymbolAddress((void**)&wqkv,  g_wqkv16);
    cudaGetSymbolAddress((void**)&wproj, g_wproj16);
    cudaGetSymbolAddress((void**)&w1,    g_w116);
    cudaGetSymbolAddress((void**)&w2,    g_w216);
    cudaGetSymbolAddress((void**)&b2,    g_bias2);

    cudaFuncSetAttribute(gemm16_kernel<0>, cudaFuncAttributeMaxDynamicSharedMemorySize, GSMEM);
    cudaFuncSetAttribute(gemm16_kernel<1>, cudaFuncAttributeMaxDynamicSharedMemorySize, GSMEM);
    cudaFuncSetAttribute(gemm16_kernel<2>, cudaFuncAttributeMaxDynamicSharedMemorySize, GSMEM);

    // --- prepack weights (fp16) ---
    wconv_kernel<<<(CQKV * CH / 4 + 255) / 256, 256>>>(qkv_w, wqkv, CQKV * CH / 4);
    prepack_proj_kernel<<<(CH * C3 + 255) / 256, 256>>>(proj_w, proj_b, focus);
    wconv_kernel<<<(MLPH * CH / 4 + 255) / 256, 256>>>(mlp_w1, w1, MLPH * CH / 4);
    wconv_kernel<<<(CH * MLPH / 4 + 255) / 256, 256>>>(mlp_w2, w2, CH * MLPH / 4);

    // 1) h = LN1(x) -> fp16
    ln_kernel<<<MROWS, 256>>>(x, ln1_w, ln1_b, h16);
    // 2) qkv16 = h @ qkv_w^T  (fp16, fp16 out)
    gemm16_kernel<0><<<dim3(CQKV / 128, MROWS / 128), 256, GSMEM>>>(
        h16, wqkv, nullptr, nullptr, qkv16, MROWS, CQKV, CH);
    // 3) attention (fp16 in/out, focus-scaled)
    attn_tc_kernel<<<dim3(SEQ / 128, BB * NH, 3), 256>>>(qkv16, focus, ocat16);
    // 4) x2 = x + ocat @ projw^T + bias2  (fp16, f32 out)
    gemm16_kernel<1><<<dim3(CH / 128, MROWS / 128), 256, GSMEM>>>(
        ocat16, wproj, b2, x, x2, MROWS, CH, C3);
    // 5) h2 = LN2(x2) -> fp16
    ln_kernel<<<MROWS, 256>>>(x2, ln2_w, ln2_b, h16);
    // 6) mlp16 = gelu(h2 @ w1^T + b1)  (fp16 out)
    gemm16_kernel<2><<<dim3(MLPH / 128, MROWS / 128), 256, GSMEM>>>(
        h16, w1, mlp_b1, nullptr, mlp16, MROWS, MLPH, CH);
    // 7) out = x2 + mlp16 @ w2^T + b2  (f32 out)
    gemm16_kernel<1><<<dim3(CH / 128, MROWS / 128), 256, GSMEM>>>(
        mlp16, w2, mlp_b2, x2, out, MROWS, CH, MLPH);
}

// round 7
// speedup vs baseline: 7.1733x; 1.0145x over previous
#include <cuda_runtime.h>
#include <cuda_fp16.h>
#include <math.h>
#include <stdint.h>

// Problem constants
#define BB    8
#define SEQ   1024
#define CH    768
#define NH    12
#define HDIM  64
#define MROWS (BB*SEQ)      // 8192
#define C3    (3*CH)        // 2304
#define CQKV  (3*C3)        // 6912
#define MLPH  (4*CH)        // 3072

// ---------------------------------------------------------------------------
// Scratch buffers
// ---------------------------------------------------------------------------
__device__ __half g_h16   [(size_t)MROWS * CH];
__device__ __half g_qkv16 [(size_t)MROWS * CQKV];
__device__ __half g_ocat16[(size_t)MROWS * C3];
__device__ __half g_mlp16 [(size_t)MROWS * MLPH];
__device__ float  g_x2    [(size_t)MROWS * CH];
__device__ __half g_wqkv16[(size_t)CQKV * CH];
__device__ __half g_wproj16[(size_t)CH * C3];
__device__ __half g_w116  [(size_t)MLPH * CH];
__device__ __half g_w216  [(size_t)CH * MLPH];
__device__ float  g_bias2 [CH];

// ---------------------------------------------------------------------------
// PTX helpers
// ---------------------------------------------------------------------------
__device__ __forceinline__ uint32_t smem_u32(const void* p) {
    uint32_t a;
    asm("{ .reg .u64 t; cvta.to.shared.u64 t, %1; cvt.u32.u64 %0, t; }" : "=r"(a) : "l"(p));
    return a;
}
__device__ __forceinline__ void ldsm4(uint32_t* r, uint32_t addr) {
    asm volatile("ldmatrix.sync.aligned.m8n8.x4.shared.b16 {%0,%1,%2,%3}, [%4];"
        : "=r"(r[0]), "=r"(r[1]), "=r"(r[2]), "=r"(r[3]) : "r"(addr));
}
__device__ __forceinline__ void ldsm4t(uint32_t* r, uint32_t addr) {
    asm volatile("ldmatrix.sync.aligned.m8n8.x4.trans.shared.b16 {%0,%1,%2,%3}, [%4];"
        : "=r"(r[0]), "=r"(r[1]), "=r"(r[2]), "=r"(r[3]) : "r"(addr));
}
__device__ __forceinline__ void ldsm2(uint32_t* r, uint32_t addr) {
    asm volatile("ldmatrix.sync.aligned.m8n8.x2.shared.b16 {%0,%1}, [%2];"
        : "=r"(r[0]), "=r"(r[1]) : "r"(addr));
}
__device__ __forceinline__ void mma16816(float* c, const uint32_t* a, const uint32_t* b) {
    asm volatile(
        "mma.sync.aligned.m16n8k16.row.col.f32.f16.f16.f32 "
        "{%0,%1,%2,%3}, {%4,%5,%6,%7}, {%8,%9}, {%0,%1,%2,%3};"
        : "+f"(c[0]), "+f"(c[1]), "+f"(c[2]), "+f"(c[3])
        : "r"(a[0]), "r"(a[1]), "r"(a[2]), "r"(a[3]), "r"(b[0]), "r"(b[1]));
}
__device__ __forceinline__ void mma16816r(float* c, const uint32_t* a, uint32_t b0, uint32_t b1) {
    asm volatile(
        "mma.sync.aligned.m16n8k16.row.col.f32.f16.f16.f32 "
        "{%0,%1,%2,%3}, {%4,%5,%6,%7}, {%8,%9}, {%0,%1,%2,%3};"
        : "+f"(c[0]), "+f"(c[1]), "+f"(c[2]), "+f"(c[3])
        : "r"(a[0]), "r"(a[1]), "r"(a[2]), "r"(a[3]), "r"(b0), "r"(b1));
}
__device__ __forceinline__ uint32_t pack_h2(float lo, float hi) {
    __half2 p = __floats2half2_rn(lo, hi);
    return *(uint32_t*)&p;
}
__device__ __forceinline__ void cp16(uint32_t saddr, const void* gptr) {
    asm volatile("cp.async.ca.shared.global [%0], [%1], 16;" :: "r"(saddr), "l"(gptr));
}
#define CP_COMMIT() asm volatile("cp.async.commit_group;")
#define CP_WAIT2()  asm volatile("cp.async.wait_group 2;")
#define CP_WAIT1()  asm volatile("cp.async.wait_group 1;")
#define CP_WAIT0()  asm volatile("cp.async.wait_group 0;")

__device__ __forceinline__ float gelu_f(float v) {
    return 0.5f * v * (1.0f + erff(v * 0.70710678118654752f));
}

// ---------------------------------------------------------------------------
// LayerNorm -> fp16
// ---------------------------------------------------------------------------
__global__ void __launch_bounds__(256) ln_kernel(const float* __restrict__ x,
                                                 const float* __restrict__ w,
                                                 const float* __restrict__ b,
                                                 __half* __restrict__ hout)
{
    __shared__ float red[2][8];
    const int row = blockIdx.x;
    const float* xr = x + (size_t)row * CH;
    const int t = threadIdx.x;
    float v0 = xr[t], v1 = xr[t + 256], v2 = xr[t + 512];
    float s  = v0 + v1 + v2;
    float sq = v0*v0 + v1*v1 + v2*v2;
    #pragma unroll
    for (int o = 16; o > 0; o >>= 1) {
        s  += __shfl_xor_sync(0xffffffff, s,  o);
        sq += __shfl_xor_sync(0xffffffff, sq, o);
    }
    const int warp = t >> 5, lane = t & 31;
    if (lane == 0) { red[0][warp] = s; red[1][warp] = sq; }
    __syncthreads();
    if (warp == 0) {
        s = red[0][lane & 7]; sq = red[1][lane & 7];
        #pragma unroll
        for (int o = 4; o > 0; o >>= 1) {
            s  += __shfl_xor_sync(0xffffffff, s,  o);
            sq += __shfl_xor_sync(0xffffffff, sq, o);
        }
        if (lane == 0) { red[0][0] = s; red[1][0] = sq; }
    }
    __syncthreads();
    const float mu  = red[0][0] * (1.0f / CH);
    float var = red[1][0] * (1.0f / CH) - mu * mu;
    var = fmaxf(var, 0.0f);
    const float inv = rsqrtf(var + 1e-5f);
    __half* orow = hout + (size_t)row * CH;
    orow[t]       = __float2half_rn((v0 - mu) * inv * w[t]       + b[t]);
    orow[t + 256] = __float2half_rn((v1 - mu) * inv * w[t + 256] + b[t + 256]);
    orow[t + 512] = __float2half_rn((v2 - mu) * inv * w[t + 512] + b[t + 512]);
}

// ---------------------------------------------------------------------------
// Weight convert / prepack
// ---------------------------------------------------------------------------
__global__ void __launch_bounds__(256) wconv_kernel(const float* __restrict__ src,
                                                    __half* __restrict__ dst, int n4)
{
    const int i = blockIdx.x * 256 + threadIdx.x;
    if (i < n4) {
        float4 v = *(const float4*)(src + (size_t)i * 4);
        *(uint2*)(dst + (size_t)i * 4) = make_uint2(pack_h2(v.x, v.y), pack_h2(v.z, v.w));
    }
}

__global__ void __launch_bounds__(256) prepack_proj_kernel(const float* __restrict__ proj_w,
                                                           const float* __restrict__ proj_b,
                                                           const float* __restrict__ focus_w)
{
    const int idx = blockIdx.x * 256 + threadIdx.x;
    const int total = CH * C3;
    if (idx < total) {
        const int c   = idx / C3;
        const int rem = idx % C3;
        const int s   = rem / CH;
        const int k   = rem % CH;
        g_wproj16[idx] = __float2half_rn(proj_w[((size_t)s * CH + c) * CH + k]);
    }
    if (idx < CH) {
        float acc = 0.0f;
        #pragma unroll
        for (int s = 0; s < 3; s++) acc += focus_w[s] * proj_b[s * CH + idx];
        g_bias2[idx] = acc;
    }
}

// ---------------------------------------------------------------------------
// Standard GEMM (128x128 tile, warp 64x32) — for narrow-N GEMMs (proj, MLP2)
// MODE 1: +bias+resid -> f32 out
// ---------------------------------------------------------------------------
#define PITCH_B 80
#define MAT_SM  (128 * PITCH_B)
#define STAGE_B (2 * MAT_SM)
#define NSTAGE  4
#define GSMEM   (NSTAGE * STAGE_B)   // 81920

template<int MODE>
__global__ void __launch_bounds__(256, 2) gemm16_kernel(
    const __half* __restrict__ A, const __half* __restrict__ B,
    const float* __restrict__ bias, const float* __restrict__ resid,
    void* __restrict__ Cout, int M, int N, int K)
{
    extern __shared__ __align__(16) char dynsm[];
    const uint32_t sb = smem_u32(dynsm);
    const int tid  = threadIdx.x;
    const int lane = tid & 31;
    const int wid  = tid >> 5;
    const int wm   = wid >> 2;
    const int wn   = wid & 3;
    const int bm = blockIdx.y * 128;
    const int bn = blockIdx.x * 128;

    const __half* Abase = A + (size_t)bm * K;
    const __half* Bbase = B + (size_t)bn * K;

    float acc[4][4][4];
    #pragma unroll
    for (int i = 0; i < 4; i++)
        #pragma unroll
        for (int j = 0; j < 4; j++)
            #pragma unroll
            for (int q = 0; q < 4; q++) acc[i][j][q] = 0.0f;

    const uint32_t a_off = (uint32_t)(wm * 64 + (lane & 15)) * PITCH_B + (lane >> 4) * 16;
    const uint32_t b_off = (uint32_t)(wn * 32 + (lane & 7)) * PITCH_B + ((lane >> 3) & 1) * 16;

    const int nchunk = K >> 5;

    auto load_chunk = [&](int ic, int stg) {
        const int k0 = ic << 5;
        const uint32_t sbase = sb + stg * STAGE_B;
        #pragma unroll
        for (int it = 0; it < 4; it++) {
            const int id = tid + it * 256;
            const int m  = id >> 9;
            const int rr = (id >> 2) & 127;
            const int c  = id & 3;
            cp16(sbase + m * MAT_SM + rr * PITCH_B + c * 16,
                 (m ? Bbase : Abase) + (size_t)rr * K + k0 + c * 8);
        }
    };

    #pragma unroll
    for (int i = 0; i < NSTAGE - 1; i++) { load_chunk(i, i); CP_COMMIT(); }

    for (int ic = 0; ic < nchunk; ic++) {
        const int rem = nchunk - 1 - ic;
        if (rem >= 2) CP_WAIT2(); else if (rem == 1) CP_WAIT1(); else CP_WAIT0();
        __syncthreads();
        if (ic + NSTAGE - 1 < nchunk) {
            load_chunk(ic + NSTAGE - 1, (ic + NSTAGE - 1) & (NSTAGE - 1));
            CP_COMMIT();
        }
        const uint32_t base = sb + (ic & (NSTAGE - 1)) * STAGE_B;
        #pragma unroll
        for (int ks = 0; ks < 2; ks++) {
            const uint32_t kso = ks * 32;
            uint32_t af[4][4], bf[4][2];
            #pragma unroll
            for (int am = 0; am < 4; am++)
                ldsm4(af[am], base + a_off + kso + am * 16 * PITCH_B);
            #pragma unroll
            for (int an = 0; an < 4; an++)
                ldsm2(bf[an], base + MAT_SM + b_off + kso + an * 8 * PITCH_B);
            #pragma unroll
            for (int am = 0; am < 4; am++)
                #pragma unroll
                for (int an = 0; an < 4; an++)
                    mma16816(acc[am][an], af[am], bf[an]);
        }
        __syncthreads();
    }

    #pragma unroll
    for (int am = 0; am < 4; am++) {
        const int r0 = bm + wm * 64 + am * 16 + (lane >> 2);
        #pragma unroll
        for (int rr = 0; rr < 2; rr++) {
            const int r = r0 + rr * 8;
            #pragma unroll
            for (int an = 0; an < 4; an++) {
                const int col = bn + wn * 32 + an * 8 + 2 * (lane & 3);
                float v0 = acc[am][an][rr * 2 + 0];
                float v1 = acc[am][an][rr * 2 + 1];
                v0 += bias[col] + resid[(size_t)r * N + col];
                v1 += bias[col + 1] + resid[(size_t)r * N + col + 1];
                *(float2*)((float*)Cout + (size_t)r * N + col) = make_float2(v0, v1);
            }
        }
    }
}

// ---------------------------------------------------------------------------
// Big-tile GEMM (128x256 block, warp 64x64) — for wide-N GEMMs (QKV, MLP1)
// MODE 0: plain -> fp16 out    MODE 2: gelu(.+bias) -> fp16 out
// ---------------------------------------------------------------------------
#define A_SMB   (128 * PITCH_B)           // 10240
#define B_SMB   (256 * PITCH_B)           // 20480
#define BSTAGE  (A_SMB + B_SMB)           // 30720
#define BNSTAGE 4
#define BGSMEM  (BNSTAGE * BSTAGE)        // 122880

template<int MODE>
__global__ void __launch_bounds__(256, 1) gemm16_big_kernel(
    const __half* __restrict__ A, const __half* __restrict__ B,
    const float* __restrict__ bias, __half* __restrict__ Cout,
    int M, int N, int K)
{
    extern __shared__ __align__(16) char dynsm[];
    const uint32_t sb = smem_u32(dynsm);
    const int tid  = threadIdx.x;
    const int lane = tid & 31;
    const int wid  = tid >> 5;
    const int wm   = wid >> 2;       // 0..1
    const int wn   = wid & 3;        // 0..3
    const int bm = blockIdx.y * 128;
    const int bn = blockIdx.x * 256;

    const __half* Abase = A + (size_t)bm * K;
    const __half* Bbase = B + (size_t)bn * K;

    float acc[4][8][4];
    #pragma unroll
    for (int i = 0; i < 4; i++)
        #pragma unroll
        for (int j = 0; j < 8; j++)
            #pragma unroll
            for (int q = 0; q < 4; q++) acc[i][j][q] = 0.0f;

    const uint32_t a_off = (uint32_t)(wm * 64 + (lane & 15)) * PITCH_B + (lane >> 4) * 16;
    const uint32_t b_off = (uint32_t)(wn * 64 + (lane & 15)) * PITCH_B + (lane >> 4) * 16;

    const int nchunk = K >> 5;

    auto load_chunk = [&](int ic, int stg) {
        const int k0 = ic << 5;
        const uint32_t sbase = sb + stg * BSTAGE;
        // A tile: 128 rows x 4 chunks = 512 cp16
        #pragma unroll
        for (int it = 0; it < 2; it++) {
            const int id = tid + it * 256;
            const int rr = id >> 2, c = id & 3;
            cp16(sbase + rr * PITCH_B + c * 16, Abase + (size_t)rr * K + k0 + c * 8);
        }
        // B tile: 256 rows x 4 chunks = 1024 cp16
        #pragma unroll
        for (int it = 0; it < 4; it++) {
            const int id = tid + it * 256;
            const int rr = id >> 2, c = id & 3;
            cp16(sbase + A_SMB + rr * PITCH_B + c * 16, Bbase + (size_t)rr * K + k0 + c * 8);
        }
    };

    #pragma unroll
    for (int i = 0; i < BNSTAGE - 1; i++) { load_chunk(i, i); CP_COMMIT(); }

    for (int ic = 0; ic < nchunk; ic++) {
        const int rem = nchunk - 1 - ic;
        if (rem >= 2) CP_WAIT2(); else if (rem == 1) CP_WAIT1(); else CP_WAIT0();
        __syncthreads();
        if (ic + BNSTAGE - 1 < nchunk) {
            load_chunk(ic + BNSTAGE - 1, (ic + BNSTAGE - 1) & (BNSTAGE - 1));
            CP_COMMIT();
        }
        const uint32_t base = sb + (ic & (BNSTAGE - 1)) * BSTAGE;
        #pragma unroll
        for (int ks = 0; ks < 2; ks++) {
            const uint32_t kso = ks * 32;
            uint32_t af[4][4], bf[4][4];
            #pragma unroll
            for (int am = 0; am < 4; am++)
                ldsm4(af[am], base + a_off + kso + am * 16 * PITCH_B);
            #pragma unroll
            for (int g = 0; g < 4; g++)
                ldsm4(bf[g], base + A_SMB + b_off + kso + g * 16 * PITCH_B);
            #pragma unroll
            for (int am = 0; am < 4; am++)
                #pragma unroll
                for (int g = 0; g < 4; g++) {
                    mma16816r(acc[am][2 * g],     af[am], bf[g][0], bf[g][2]);
                    mma16816r(acc[am][2 * g + 1], af[am], bf[g][1], bf[g][3]);
                }
        }
        __syncthreads();
    }

    // ---- epilogue ----
    #pragma unroll
    for (int am = 0; am < 4; am++) {
        const int r0 = bm + wm * 64 + am * 16 + (lane >> 2);
        #pragma unroll
        for (int rr = 0; rr < 2; rr++) {
            const int r = r0 + rr * 8;
            #pragma unroll
            for (int j = 0; j < 8; j++) {
                const int col = bn + wn * 64 + j * 8 + 2 * (lane & 3);
                float v0 = acc[am][j][rr * 2 + 0];
                float v1 = acc[am][j][rr * 2 + 1];
                if (MODE == 2) {
                    v0 = gelu_f(v0 + bias[col]);
                    v1 = gelu_f(v1 + bias[col + 1]);
                }
                *(uint32_t*)(Cout + (size_t)r * N + col) = pack_h2(v0, v1);
            }
        }
    }
}

// ---------------------------------------------------------------------------
// Tensor-core flash attention, cp.async double-buffered KV (dynamic smem).
// 256 threads = 8 warps x 16 q-rows = 128-row Q tile; KV tiles of 64 keys.
// ---------------------------------------------------------------------------
#define APITCH  144
#define Q_SMB   (128 * APITCH)            // 18432
#define KV_SMB  (128 * APITCH)            // K(64)+V(64) per buffer
#define ASMEM   (Q_SMB + 2 * KV_SMB)      // 55296

__global__ void __launch_bounds__(256) attn_tc_kernel(
    const __half* __restrict__ qkv16, const float* __restrict__ focus_w,
    __half* __restrict__ ocat16)
{
    extern __shared__ __align__(16) char dynsm[];
    char* Qs = dynsm;
    const uint32_t qsb = smem_u32(Qs);
    const uint32_t kvsb = qsb + Q_SMB;

    const int s  = blockIdx.z;
    const int b  = blockIdx.y / NH;
    const int hh = blockIdx.y % NH;
    const int t  = threadIdx.x;
    const int lane = t & 31, w = t >> 5;
    const int q0 = blockIdx.x * 128;

    const __half* kvb = qkv16 + (size_t)b * SEQ * CQKV + s * C3 + CH + hh * HDIM;

    // cp.async KV tile loader: 1024 cp16 per tile (K 64x8, V 64x8)
    auto load_kv = [&](int kt, int buf) {
        const uint32_t dst = kvsb + buf * KV_SMB;
        #pragma unroll
        for (int it = 0; it < 4; it++) {
            const int id = t + it * 256;
            const int mm = id >> 9;           // 0: K, 1: V
            const int rr = (id >> 3) & 63;
            const int c  = id & 7;
            cp16(dst + mm * (64 * APITCH) + rr * APITCH + c * 16,
                 kvb + (size_t)(kt + rr) * CQKV + mm * CH + c * 8);
        }
    };

    // ---- load Q tile [128][64] fp16 (regular loads) + first KV via cp.async ----
    load_kv(0, 0);
    CP_COMMIT();
    {
        const __half* qptr = qkv16 + (size_t)(b * SEQ + q0) * CQKV + s * C3 + hh * HDIM;
        #pragma unroll
        for (int it = 0; it < 4; it++) {
            const int idx = t + it * 256;
            const int r = idx >> 3, c = idx & 7;
            *(uint4*)(Qs + r * APITCH + c * 16) =
                *(const uint4*)(qptr + (size_t)r * CQKV + c * 8);
        }
    }
    __syncthreads();
    uint32_t qf[4][4];
    #pragma unroll
    for (int kc = 0; kc < 4; kc++)
        ldsm4(qf[kc], qsb + (uint32_t)(w * 16 + (lane & 15)) * APITCH + kc * 32 + (lane >> 4) * 16);

    float of[8][4];
    #pragma unroll
    for (int dn = 0; dn < 8; dn++)
        #pragma unroll
        for (int q = 0; q < 4; q++) of[dn][q] = 0.0f;
    float m0 = -1e30f, m1 = -1e30f, l0 = 0.0f, l1 = 0.0f;
    const float scale = 0.125f;

    const int NTILE = SEQ / 64;
    for (int it = 0; it < NTILE; it++) {
        if (it + 1 < NTILE) {
            load_kv((it + 1) * 64, (it + 1) & 1);
            CP_COMMIT();
            CP_WAIT1();
        } else {
            CP_WAIT0();
        }
        __syncthreads();
        const uint32_t ksb = kvsb + (it & 1) * KV_SMB;
        const uint32_t vsb = ksb + 64 * APITCH;

        // ---- S = Q @ K^T ----
        float sf[8][4];
        #pragma unroll
        for (int j = 0; j < 8; j++)
            #pragma unroll
            for (int q = 0; q < 4; q++) sf[j][q] = 0.0f;
        #pragma unroll
        for (int kc = 0; kc < 4; kc++) {
            #pragma unroll
            for (int np = 0; np < 4; np++) {
                uint32_t kb4[4];
                ldsm4(kb4, ksb + (uint32_t)(np * 16 + (lane & 7) + ((lane >> 4) << 3)) * APITCH
                              + kc * 32 + (((lane >> 3) & 1) << 4));
                mma16816(sf[2 * np],     qf[kc], kb4);
                mma16816(sf[2 * np + 1], qf[kc], kb4 + 2);
            }
        }

        // ---- online softmax ----
        float rmax0 = -1e30f, rmax1 = -1e30f;
        #pragma unroll
        for (int j = 0; j < 8; j++) {
            rmax0 = fmaxf(rmax0, fmaxf(sf[j][0], sf[j][1]));
            rmax1 = fmaxf(rmax1, fmaxf(sf[j][2], sf[j][3]));
        }
        rmax0 = fmaxf(rmax0, __shfl_xor_sync(0xffffffff, rmax0, 1));
        rmax0 = fmaxf(rmax0, __shfl_xor_sync(0xffffffff, rmax0, 2));
        rmax1 = fmaxf(rmax1, __shfl_xor_sync(0xffffffff, rmax1, 1));
        rmax1 = fmaxf(rmax1, __shfl_xor_sync(0xffffffff, rmax1, 2));
        const float mn0 = fmaxf(m0, rmax0 * scale);
        const float mn1 = fmaxf(m1, rmax1 * scale);
        const float a0 = __expf(m0 - mn0);
        const float a1 = __expf(m1 - mn1);
        float rs0 = 0.0f, rs1 = 0.0f;
        #pragma unroll
        for (int j = 0; j < 8; j++) {
            sf[j][0] = __expf(fmaf(sf[j][0], scale, -mn0));
            sf[j][1] = __expf(fmaf(sf[j][1], scale, -mn0));
            sf[j][2] = __expf(fmaf(sf[j][2], scale, -mn1));
            sf[j][3] = __expf(fmaf(sf[j][3], scale, -mn1));
            rs0 += sf[j][0] + sf[j][1];
            rs1 += sf[j][2] + sf[j][3];
        }
        rs0 += __shfl_xor_sync(0xffffffff, rs0, 1);
        rs0 += __shfl_xor_sync(0xffffffff, rs0, 2);
        rs1 += __shfl_xor_sync(0xffffffff, rs1, 1);
        rs1 += __shfl_xor_sync(0xffffffff, rs1, 2);
        l0 = l0 * a0 + rs0;
        l1 = l1 * a1 + rs1;
        m0 = mn0; m1 = mn1;
        #pragma unroll
        for (int dn = 0; dn < 8; dn++) {
            of[dn][0] *= a0; of[dn][1] *= a0;
            of[dn][2] *= a1; of[dn][3] *= a1;
        }

        // ---- O += P @ V ----
        #pragma unroll
        for (int kc = 0; kc < 4; kc++) {
            uint32_t pa[4];
            pa[0] = pack_h2(sf[2 * kc][0],     sf[2 * kc][1]);
            pa[1] = pack_h2(sf[2 * kc][2],     sf[2 * kc][3]);
            pa[2] = pack_h2(sf[2 * kc + 1][0], sf[2 * kc + 1][1]);
            pa[3] = pack_h2(sf[2 * kc + 1][2], sf[2 * kc + 1][3]);
            #pragma unroll
            for (int dp = 0; dp < 4; dp++) {
                uint32_t vb4[4];
                ldsm4t(vb4, vsb + (uint32_t)(kc * 16 + (lane & 15)) * APITCH
                               + dp * 32 + (lane >> 4) * 16);
                mma16816(of[2 * dp],     pa, vb4);
                mma16816(of[2 * dp + 1], pa, vb4 + 2);
            }
        }
        __syncthreads();
    }

    // ---- write focus-scaled, normalized fp16 output ----
    const float f = focus_w[s];
    const float inv0 = f / l0, inv1 = f / l1;
    const int r0 = q0 + w * 16 + (lane >> 2);
    __half* dst0 = ocat16 + (size_t)(b * SEQ + r0) * C3 + s * CH + hh * HDIM;
    __half* dst1 = dst0 + (size_t)8 * C3;
    #pragma unroll
    for (int dn = 0; dn < 8; dn++) {
        const int col = dn * 8 + 2 * (lane & 3);
        *(uint32_t*)(dst0 + col) = pack_h2(of[dn][0] * inv0, of[dn][1] * inv0);
        *(uint32_t*)(dst1 + col) = pack_h2(of[dn][2] * inv1, of[dn][3] * inv1);
    }
}

// ---------------------------------------------------------------------------
// Launch
// ---------------------------------------------------------------------------
extern "C" void kernel_launch(void* const* d_in, const int* in_sizes, int n_in,
                              void* d_out, int out_size)
{
    const float* x      = (const float*)d_in[0];
    const float* qkv_w  = (const float*)d_in[1];
    const float* proj_w = (const float*)d_in[2];
    const float* proj_b = (const float*)d_in[3];
    const float* ln1_w  = (const float*)d_in[4];
    const float* ln1_b  = (const float*)d_in[5];
    const float* ln2_w  = (const float*)d_in[6];
    const float* ln2_b  = (const float*)d_in[7];
    const float* mlp_w1 = (const float*)d_in[8];
    const float* mlp_b1 = (const float*)d_in[9];
    const float* mlp_w2 = (const float*)d_in[10];
    const float* mlp_b2 = (const float*)d_in[11];
    const float* focus  = (const float*)d_in[12];
    float* out = (float*)d_out;

    __half *h16, *qkv16, *ocat16, *mlp16, *wqkv, *wproj, *w1, *w2;
    float *x2, *b2;
    cudaGetSymbolAddress((void**)&h16,   g_h16);
    cudaGetSymbolAddress((void**)&qkv16, g_qkv16);
    cudaGetSymbolAddress((void**)&ocat16,g_ocat16);
    cudaGetSymbolAddress((void**)&mlp16, g_mlp16);
    cudaGetSymbolAddress((void**)&x2,    g_x2);
    cudaGetSymbolAddress((void**)&wqkv,  g_wqkv16);
    cudaGetSymbolAddress((void**)&wproj, g_wproj16);
    cudaGetSymbolAddress((void**)&w1,    g_w116);
    cudaGetSymbolAddress((void**)&w2,    g_w216);
    cudaGetSymbolAddress((void**)&b2,    g_bias2);

    cudaFuncSetAttribute(gemm16_kernel<1>,     cudaFuncAttributeMaxDynamicSharedMemorySize, GSMEM);
    cudaFuncSetAttribute(gemm16_big_kernel<0>, cudaFuncAttributeMaxDynamicSharedMemorySize, BGSMEM);
    cudaFuncSetAttribute(gemm16_big_kernel<2>, cudaFuncAttributeMaxDynamicSharedMemorySize, BGSMEM);
    cudaFuncSetAttribute(attn_tc_kernel,       cudaFuncAttributeMaxDynamicSharedMemorySize, ASMEM);

    // --- prepack weights (fp16) ---
    wconv_kernel<<<(CQKV * CH / 4 + 255) / 256, 256>>>(qkv_w, wqkv, CQKV * CH / 4);
    prepack_proj_kernel<<<(CH * C3 + 255) / 256, 256>>>(proj_w, proj_b, focus);
    wconv_kernel<<<(MLPH * CH / 4 + 255) / 256, 256>>>(mlp_w1, w1, MLPH * CH / 4);
    wconv_kernel<<<(CH * MLPH / 4 + 255) / 256, 256>>>(mlp_w2, w2, CH * MLPH / 4);

    // 1) h = LN1(x) -> fp16
    ln_kernel<<<MROWS, 256>>>(x, ln1_w, ln1_b, h16);
    // 2) qkv16 = h @ qkv_w^T  (big tile)
    gemm16_big_kernel<0><<<dim3(CQKV / 256, MROWS / 128), 256, BGSMEM>>>(
        h16, wqkv, nullptr, qkv16, MROWS, CQKV, CH);
    // 3) attention (fp16 in/out, focus-scaled, pipelined KV)
    attn_tc_kernel<<<dim3(SEQ / 128, BB * NH, 3), 256, ASMEM>>>(qkv16, focus, ocat16);
    // 4) x2 = x + ocat @ projw^T + bias2
    gemm16_kernel<1><<<dim3(CH / 128, MROWS / 128), 256, GSMEM>>>(
        ocat16, wproj, b2, x, x2, MROWS, CH, C3);
    // 5) h2 = LN2(x2) -> fp16
    ln_kernel<<<MROWS, 256>>>(x2, ln2_w, ln2_b, h16);
    // 6) mlp16 = gelu(h2 @ w1^T + b1)  (big tile)
    gemm16_big_kernel<2><<<dim3(MLPH / 256, MROWS / 128), 256, BGSMEM>>>(
        h16, w1, mlp_b1, mlp16, MROWS, MLPH, CH);
    // 7) out = x2 + mlp16 @ w2^T + b2
    gemm16_kernel<1><<<dim3(CH / 128, MROWS / 128), 256, GSMEM>>>(
        mlp16, w2, mlp_b2, x2, out, MROWS, CH, MLPH);
}

// round 9
// speedup vs baseline: 8.5261x; 1.1886x over previous
#include <cuda_runtime.h>
#include <cuda_fp16.h>
#include <math.h>
#include <stdint.h>

// Problem constants
#define BB    8
#define SEQ   1024
#define CH    768
#define NH    12
#define HDIM  64
#define MROWS (BB*SEQ)      // 8192
#define C3    (3*CH)        // 2304
#define CQKV  (3*C3)        // 6912
#define MLPH  (4*CH)        // 3072

// ---------------------------------------------------------------------------
// Scratch buffers
// g_qkv16 is head-major: plane(s,t,b,h) = ((s*3+t)*BB+b)*NH+h ; [plane][seq][64]
// ---------------------------------------------------------------------------
__device__ __half g_h16   [(size_t)MROWS * CH];
__device__ __half g_qkv16 [(size_t)MROWS * CQKV];
__device__ __half g_ocat16[(size_t)MROWS * C3];
__device__ __half g_mlp16 [(size_t)MROWS * MLPH];
__device__ float  g_x2    [(size_t)MROWS * CH];
__device__ __half g_wqkv16[(size_t)CQKV * CH];
__device__ __half g_wproj16[(size_t)CH * C3];
__device__ __half g_w116  [(size_t)MLPH * CH];
__device__ __half g_w216  [(size_t)CH * MLPH];
__device__ float  g_bias2 [CH];

// ---------------------------------------------------------------------------
// PTX helpers
// ---------------------------------------------------------------------------
__device__ __forceinline__ uint32_t smem_u32(const void* p) {
    uint32_t a;
    asm("{ .reg .u64 t; cvta.to.shared.u64 t, %1; cvt.u32.u64 %0, t; }" : "=r"(a) : "l"(p));
    return a;
}
__device__ __forceinline__ void ldsm4(uint32_t* r, uint32_t addr) {
    asm volatile("ldmatrix.sync.aligned.m8n8.x4.shared.b16 {%0,%1,%2,%3}, [%4];"
        : "=r"(r[0]), "=r"(r[1]), "=r"(r[2]), "=r"(r[3]) : "r"(addr));
}
__device__ __forceinline__ void ldsm4t(uint32_t* r, uint32_t addr) {
    asm volatile("ldmatrix.sync.aligned.m8n8.x4.trans.shared.b16 {%0,%1,%2,%3}, [%4];"
        : "=r"(r[0]), "=r"(r[1]), "=r"(r[2]), "=r"(r[3]) : "r"(addr));
}
__device__ __forceinline__ void ldsm2(uint32_t* r, uint32_t addr) {
    asm volatile("ldmatrix.sync.aligned.m8n8.x2.shared.b16 {%0,%1}, [%2];"
        : "=r"(r[0]), "=r"(r[1]) : "r"(addr));
}
__device__ __forceinline__ void mma16816(float* c, const uint32_t* a, const uint32_t* b) {
    asm volatile(
        "mma.sync.aligned.m16n8k16.row.col.f32.f16.f16.f32 "
        "{%0,%1,%2,%3}, {%4,%5,%6,%7}, {%8,%9}, {%0,%1,%2,%3};"
        : "+f"(c[0]), "+f"(c[1]), "+f"(c[2]), "+f"(c[3])
        : "r"(a[0]), "r"(a[1]), "r"(a[2]), "r"(a[3]), "r"(b[0]), "r"(b[1]));
}
__device__ __forceinline__ uint32_t pack_h2(float lo, float hi) {
    __half2 p = __floats2half2_rn(lo, hi);
    return *(uint32_t*)&p;
}
__device__ __forceinline__ void cp16(uint32_t saddr, const void* gptr) {
    asm volatile("cp.async.ca.shared.global [%0], [%1], 16;" :: "r"(saddr), "l"(gptr));
}
#define CP_COMMIT() asm volatile("cp.async.commit_group;")
#define CP_WAIT0()  asm volatile("cp.async.wait_group 0;")

__device__ __forceinline__ float gelu_f(float v) {
    return 0.5f * v * (1.0f + erff(v * 0.70710678118654752f));
}

// ---------------------------------------------------------------------------
// LayerNorm -> fp16
// ---------------------------------------------------------------------------
__global__ void __launch_bounds__(256) ln_kernel(const float* __restrict__ x,
                                                 const float* __restrict__ w,
                                                 const float* __restrict__ b,
                                                 __half* __restrict__ hout)
{
    __shared__ float red[2][8];
    const int row = blockIdx.x;
    const float* xr = x + (size_t)row * CH;
    const int t = threadIdx.x;
    float v0 = xr[t], v1 = xr[t + 256], v2 = xr[t + 512];
    float s  = v0 + v1 + v2;
    float sq = v0*v0 + v1*v1 + v2*v2;
    #pragma unroll
    for (int o = 16; o > 0; o >>= 1) {
        s  += __shfl_xor_sync(0xffffffff, s,  o);
        sq += __shfl_xor_sync(0xffffffff, sq, o);
    }
    const int warp = t >> 5, lane = t & 31;
    if (lane == 0) { red[0][warp] = s; red[1][warp] = sq; }
    __syncthreads();
    if (warp == 0) {
        s = red[0][lane & 7]; sq = red[1][lane & 7];
        #pragma unroll
        for (int o = 4; o > 0; o >>= 1) {
            s  += __shfl_xor_sync(0xffffffff, s,  o);
            sq += __shfl_xor_sync(0xffffffff, sq, o);
        }
        if (lane == 0) { red[0][0] = s; red[1][0] = sq; }
    }
    __syncthreads();
    const float mu  = red[0][0] * (1.0f / CH);
    float var = red[1][0] * (1.0f / CH) - mu * mu;
    var = fmaxf(var, 0.0f);
    const float inv = rsqrtf(var + 1e-5f);
    __half* orow = hout + (size_t)row * CH;
    orow[t]       = __float2half_rn((v0 - mu) * inv * w[t]       + b[t]);
    orow[t + 256] = __float2half_rn((v1 - mu) * inv * w[t + 256] + b[t + 256]);
    orow[t + 512] = __float2half_rn((v2 - mu) * inv * w[t + 512] + b[t + 512]);
}

// ---------------------------------------------------------------------------
// Weight convert / prepack
// ---------------------------------------------------------------------------
__global__ void __launch_bounds__(256) wconv_kernel(const float* __restrict__ src,
                                                    __half* __restrict__ dst, int n4)
{
    const int i = blockIdx.x * 256 + threadIdx.x;
    if (i < n4) {
        float4 v = *(const float4*)(src + (size_t)i * 4);
        *(uint2*)(dst + (size_t)i * 4) = make_uint2(pack_h2(v.x, v.y), pack_h2(v.z, v.w));
    }
}

__global__ void __launch_bounds__(256) prepack_proj_kernel(const float* __restrict__ proj_w,
                                                           const float* __restrict__ proj_b,
                                                           const float* __restrict__ focus_w)
{
    const int idx = blockIdx.x * 256 + threadIdx.x;
    const int total = CH * C3;
    if (idx < total) {
        const int c   = idx / C3;
        const int rem = idx % C3;
        const int s   = rem / CH;
        const int k   = rem % CH;
        g_wproj16[idx] = __float2half_rn(proj_w[((size_t)s * CH + c) * CH + k]);
    }
    if (idx < CH) {
        float acc = 0.0f;
        #pragma unroll
        for (int s = 0; s < 3; s++) acc += focus_w[s] * proj_b[s * CH + idx];
        g_bias2[idx] = acc;
    }
}

// ---------------------------------------------------------------------------
// fp16 GEMM: 128x128 tile, Kc=64, 2-stage cp.async, ONE barrier per chunk.
// C[m,n] = sum_k A[m,k]*B[n,k]
// MODE 0: plain -> fp16 out        MODE 1: +bias+resid -> f32 out
// MODE 2: gelu(.+bias) -> fp16 out MODE 3: plain -> fp16 head-major scatter (QKV)
// ---------------------------------------------------------------------------
#define PITCH   144
#define MATB    (128 * PITCH)      // 18432
#define STAGEB  (2 * MATB)         // 36864
#define GSMEM   (2 * STAGEB)       // 73728

template<int MODE>
__global__ void __launch_bounds__(256, 2) gemm16_kernel(
    const __half* __restrict__ A, const __half* __restrict__ B,
    const float* __restrict__ bias, const float* __restrict__ resid,
    void* __restrict__ Cout, int M, int N, int K)
{
    extern __shared__ __align__(16) char dynsm[];
    const uint32_t sb = smem_u32(dynsm);
    const int tid  = threadIdx.x;
    const int lane = tid & 31;
    const int wid  = tid >> 5;
    const int wm   = wid >> 2;       // 0..1
    const int wn   = wid & 3;        // 0..3
    const int bm = blockIdx.y * 128;
    const int bn = blockIdx.x * 128;

    const __half* Abase = A + (size_t)bm * K;
    const __half* Bbase = B + (size_t)bn * K;

    float acc[4][4][4];
    #pragma unroll
    for (int i = 0; i < 4; i++)
        #pragma unroll
        for (int j = 0; j < 4; j++)
            #pragma unroll
            for (int q = 0; q < 4; q++) acc[i][j][q] = 0.0f;

    const uint32_t a_off = (uint32_t)(wm * 64 + (lane & 15)) * PITCH + (lane >> 4) * 16;
    const uint32_t b_off = (uint32_t)(wn * 32 + (lane & 7)) * PITCH + ((lane >> 3) & 1) * 16;

    const int nchunk = K >> 6;   // Kc = 64

    auto load_chunk = [&](int ic, int stg) {
        const int k0 = ic << 6;
        const uint32_t sbase = sb + stg * STAGEB;
        #pragma unroll
        for (int it = 0; it < 8; it++) {
            const int id = tid + it * 256;
            const int m  = id >> 10;          // 0: A, 1: B
            const int rr = (id >> 3) & 127;
            const int c  = id & 7;
            cp16(sbase + m * MATB + rr * PITCH + c * 16,
                 (m ? Bbase : Abase) + (size_t)rr * K + k0 + c * 8);
        }
    };

    load_chunk(0, 0);
    CP_COMMIT();

    for (int ic = 0; ic < nchunk; ic++) {
        CP_WAIT0();
        __syncthreads();
        if (ic + 1 < nchunk) {
            load_chunk(ic + 1, (ic + 1) & 1);
            CP_COMMIT();
        }
        const uint32_t base = sb + (ic & 1) * STAGEB;
        #pragma unroll
        for (int kc = 0; kc < 4; kc++) {
            const uint32_t kso = kc * 32;
            uint32_t af[4][4], bf[4][2];
            #pragma unroll
            for (int am = 0; am < 4; am++)
                ldsm4(af[am], base + a_off + kso + am * 16 * PITCH);
            #pragma unroll
            for (int an = 0; an < 4; an++)
                ldsm2(bf[an], base + MATB + b_off + kso + an * 8 * PITCH);
            #pragma unroll
            for (int am = 0; am < 4; am++)
                #pragma unroll
                for (int an = 0; an < 4; an++)
                    mma16816(acc[am][an], af[am], bf[an]);
        }
    }

    // ---- epilogue ----
    #pragma unroll
    for (int am = 0; am < 4; am++) {
        const int r0 = bm + wm * 64 + am * 16 + (lane >> 2);
        #pragma unroll
        for (int rr = 0; rr < 2; rr++) {
            const int r = r0 + rr * 8;
            #pragma unroll
            for (int an = 0; an < 4; an++) {
                const int col = bn + wn * 32 + an * 8 + 2 * (lane & 3);
                float v0 = acc[am][an][rr * 2 + 0];
                float v1 = acc[am][an][rr * 2 + 1];
                if (MODE == 0) {
                    *(uint32_t*)((__half*)Cout + (size_t)r * N + col) = pack_h2(v0, v1);
                } else if (MODE == 1) {
                    v0 += bias[col] + resid[(size_t)r * N + col];
                    v1 += bias[col + 1] + resid[(size_t)r * N + col + 1];
                    *(float2*)((float*)Cout + (size_t)r * N + col) = make_float2(v0, v1);
                } else if (MODE == 2) {
                    v0 = gelu_f(v0 + bias[col]);
                    v1 = gelu_f(v1 + bias[col + 1]);
                    *(uint32_t*)((__half*)Cout + (size_t)r * N + col) = pack_h2(v0, v1);
                } else {
                    // MODE 3: scatter to head-major [ (s*3+t)*BB+b ][ h ][seq][64]
                    const int st = col / CH;              // s*3 + t  (0..8)
                    const int rem = col - st * CH;        // 0..767
                    const int h  = rem >> 6;
                    const int d  = rem & 63;
                    const int bb = r >> 10;               // batch
                    const int n  = r & 1023;              // seq pos
                    const size_t plane = (size_t)(st * BB + bb) * NH + h;
                    *(uint32_t*)((__half*)Cout + plane * (SEQ * HDIM) + n * HDIM + d) =
                        pack_h2(v0, v1);
                }
            }
        }
    }
}

// ---------------------------------------------------------------------------
// Tensor-core flash attention, head-major QKV planes, single barrier per tile.
// 256 threads = 8 warps x 16 q-rows = 128-row Q tile; KV tiles of 64 keys.
// ---------------------------------------------------------------------------
#define Q_SMB   (128 * PITCH)            // 18432
#define KV_SMB  (128 * PITCH)            // K(64)+V(64) rows per buffer
#define ASMEM   (Q_SMB + 2 * KV_SMB)     // 55296

__global__ void __launch_bounds__(256, 2) attn_tc_kernel(
    const __half* __restrict__ qkv16, const float* __restrict__ focus_w,
    __half* __restrict__ ocat16)
{
    extern __shared__ __align__(16) char dynsm[];
    char* Qs = dynsm;
    const uint32_t qsb = smem_u32(Qs);
    const uint32_t kvsb = qsb + Q_SMB;

    const int s  = blockIdx.z;
    const int b  = blockIdx.y / NH;
    const int hh = blockIdx.y % NH;
    const int t  = threadIdx.x;
    const int lane = t & 31, w = t >> 5;
    const int q0 = blockIdx.x * 128;

    // head-major plane bases
    const size_t qplane = ((size_t)(s * 3 + 0) * BB + b) * NH + hh;
    const size_t kplane = ((size_t)(s * 3 + 1) * BB + b) * NH + hh;
    const size_t vplane = ((size_t)(s * 3 + 2) * BB + b) * NH + hh;
    const __half* Qg = qkv16 + qplane * (SEQ * HDIM);
    const __half* Kg = qkv16 + kplane * (SEQ * HDIM);
    const __half* Vg = qkv16 + vplane * (SEQ * HDIM);

    // KV tile loader: contiguous 8KB per matrix, 1024 cp16 total
    auto load_kv = [&](int kt, int buf) {
        const uint32_t dst = kvsb + buf * KV_SMB;
        #pragma unroll
        for (int it = 0; it < 4; it++) {
            const int id = t + it * 256;
            const int mm = id >> 9;           // 0: K, 1: V
            const int rr = (id >> 3) & 63;
            const int c  = id & 7;
            cp16(dst + mm * (64 * PITCH) + rr * PITCH + c * 16,
                 (mm ? Vg : Kg) + (size_t)(kt + rr) * HDIM + c * 8);
        }
    };

    load_kv(0, 0);
    CP_COMMIT();
    // Q tile: contiguous rows
    #pragma unroll
    for (int it = 0; it < 4; it++) {
        const int idx = t + it * 256;
        const int r = idx >> 3, c = idx & 7;
        *(uint4*)(Qs + r * PITCH + c * 16) = *(const uint4*)(Qg + (size_t)(q0 + r) * HDIM + c * 8);
    }
    __syncthreads();
    uint32_t qf[4][4];
    #pragma unroll
    for (int kc = 0; kc < 4; kc++)
        ldsm4(qf[kc], qsb + (uint32_t)(w * 16 + (lane & 15)) * PITCH + kc * 32 + (lane >> 4) * 16);

    float of[8][4];
    #pragma unroll
    for (int dn = 0; dn < 8; dn++)
        #pragma unroll
        for (int q = 0; q < 4; q++) of[dn][q] = 0.0f;
    float m0 = -1e30f, m1 = -1e30f, l0 = 0.0f, l1 = 0.0f;
    const float scale = 0.125f;

    const int NTILE = SEQ / 64;
    for (int it = 0; it < NTILE; it++) {
        CP_WAIT0();
        __syncthreads();
        if (it + 1 < NTILE) {
            load_kv((it + 1) * 64, (it + 1) & 1);
            CP_COMMIT();
        }
        const uint32_t ksb = kvsb + (it & 1) * KV_SMB;
        const uint32_t vsb = ksb + 64 * PITCH;

        // ---- S = Q @ K^T ----
        float sf[8][4];
        #pragma unroll
        for (int j = 0; j < 8; j++)
            #pragma unroll
            for (int q = 0; q < 4; q++) sf[j][q] = 0.0f;
        #pragma unroll
        for (int kc = 0; kc < 4; kc++) {
            #pragma unroll
            for (int np = 0; np < 4; np++) {
                uint32_t kb4[4];
                ldsm4(kb4, ksb + (uint32_t)(np * 16 + (lane & 7) + ((lane >> 4) << 3)) * PITCH
                              + kc * 32 + (((lane >> 3) & 1) << 4));
                mma16816(sf[2 * np],     qf[kc], kb4);
                mma16816(sf[2 * np + 1], qf[kc], kb4 + 2);
            }
        }

        // ---- online softmax ----
        float rmax0 = -1e30f, rmax1 = -1e30f;
        #pragma unroll
        for (int j = 0; j < 8; j++) {
            rmax0 = fmaxf(rmax0, fmaxf(sf[j][0], sf[j][1]));
            rmax1 = fmaxf(rmax1, fmaxf(sf[j][2], sf[j][3]));
        }
        rmax0 = fmaxf(rmax0, __shfl_xor_sync(0xffffffff, rmax0, 1));
        rmax0 = fmaxf(rmax0, __shfl_xor_sync(0xffffffff, rmax0, 2));
        rmax1 = fmaxf(rmax1, __shfl_xor_sync(0xffffffff, rmax1, 1));
        rmax1 = fmaxf(rmax1, __shfl_xor_sync(0xffffffff, rmax1, 2));
        const float mn0 = fmaxf(m0, rmax0 * scale);
        const float mn1 = fmaxf(m1, rmax1 * scale);
        const float a0 = __expf(m0 - mn0);
        const float a1 = __expf(m1 - mn1);
        float rs0 = 0.0f, rs1 = 0.0f;
        #pragma unroll
        for (int j = 0; j < 8; j++) {
            sf[j][0] = __expf(fmaf(sf[j][0], scale, -mn0));
            sf[j][1] = __expf(fmaf(sf[j][1], scale, -mn0));
            sf[j][2] = __expf(fmaf(sf[j][2], scale, -mn1));
            sf[j][3] = __expf(fmaf(sf[j][3], scale, -mn1));
            rs0 += sf[j][0] + sf[j][1];
            rs1 += sf[j][2] + sf[j][3];
        }
        rs0 += __shfl_xor_sync(0xffffffff, rs0, 1);
        rs0 += __shfl_xor_sync(0xffffffff, rs0, 2);
        rs1 += __shfl_xor_sync(0xffffffff, rs1, 1);
        rs1 += __shfl_xor_sync(0xffffffff, rs1, 2);
        l0 = l0 * a0 + rs0;
        l1 = l1 * a1 + rs1;
        m0 = mn0; m1 = mn1;
        #pragma unroll
        for (int dn = 0; dn < 8; dn++) {
            of[dn][0] *= a0; of[dn][1] *= a0;
            of[dn][2] *= a1; of[dn][3] *= a1;
        }

        // ---- O += P @ V ----
        #pragma unroll
        for (int kc = 0; kc < 4; kc++) {
            uint32_t pa[4];
            pa[0] = pack_h2(sf[2 * kc][0],     sf[2 * kc][1]);
            pa[1] = pack_h2(sf[2 * kc][2],     sf[2 * kc][3]);
            pa[2] = pack_h2(sf[2 * kc + 1][0], sf[2 * kc + 1][1]);
            pa[3] = pack_h2(sf[2 * kc + 1][2], sf[2 * kc + 1][3]);
            #pragma unroll
            for (int dp = 0; dp < 4; dp++) {
                uint32_t vb4[4];
                ldsm4t(vb4, vsb + (uint32_t)(kc * 16 + (lane & 15)) * PITCH
                               + dp * 32 + (lane >> 4) * 16);
                mma16816(of[2 * dp],     pa, vb4);
                mma16816(of[2 * dp + 1], pa, vb4 + 2);
            }
        }
    }

    // ---- write focus-scaled, normalized fp16 output (C3-major ocat) ----
    const float f = focus_w[s];
    const float inv0 = f / l0, inv1 = f / l1;
    const int r0 = q0 + w * 16 + (lane >> 2);
    __half* dst0 = ocat16 + (size_t)(b * SEQ + r0) * C3 + s * CH + hh * HDIM;
    __half* dst1 = dst0 + (size_t)8 * C3;
    #pragma unroll
    for (int dn = 0; dn < 8; dn++) {
        const int col = dn * 8 + 2 * (lane & 3);
        *(uint32_t*)(dst0 + col) = pack_h2(of[dn][0] * inv0, of[dn][1] * inv0);
        *(uint32_t*)(dst1 + col) = pack_h2(of[dn][2] * inv1, of[dn][3] * inv1);
    }
}

// ---------------------------------------------------------------------------
// Launch
// ---------------------------------------------------------------------------
extern "C" void kernel_launch(void* const* d_in, const int* in_sizes, int n_in,
                              void* d_out, int out_size)
{
    const float* x      = (const float*)d_in[0];
    const float* qkv_w  = (const float*)d_in[1];
    const float* proj_w = (const float*)d_in[2];
    const float* proj_b = (const float*)d_in[3];
    const float* ln1_w  = (const float*)d_in[4];
    const float* ln1_b  = (const float*)d_in[5];
    const float* ln2_w  = (const float*)d_in[6];
    const float* ln2_b  = (const float*)d_in[7];
    const float* mlp_w1 = (const float*)d_in[8];
    const float* mlp_b1 = (const float*)d_in[9];
    const float* mlp_w2 = (const float*)d_in[10];
    const float* mlp_b2 = (const float*)d_in[11];
    const float* focus  = (const float*)d_in[12];
    float* out = (float*)d_out;

    __half *h16, *qkv16, *ocat16, *mlp16, *wqkv, *wproj, *w1, *w2;
    float *x2, *b2;
    cudaGetSymbolAddress((void**)&h16,   g_h16);
    cudaGetSymbolAddress((void**)&qkv16, g_qkv16);
    cudaGetSymbolAddress((void**)&ocat16,g_ocat16);
    cudaGetSymbolAddress((void**)&mlp16, g_mlp16);
    cudaGetSymbolAddress((void**)&x2,    g_x2);
    cudaGetSymbolAddress((void**)&wqkv,  g_wqkv16);
    cudaGetSymbolAddress((void**)&wproj, g_wproj16);
    cudaGetSymbolAddress((void**)&w1,    g_w116);
    cudaGetSymbolAddress((void**)&w2,    g_w216);
    cudaGetSymbolAddress((void**)&b2,    g_bias2);

    cudaFuncSetAttribute(gemm16_kernel<1>, cudaFuncAttributeMaxDynamicSharedMemorySize, GSMEM);
    cudaFuncSetAttribute(gemm16_kernel<2>, cudaFuncAttributeMaxDynamicSharedMemorySize, GSMEM);
    cudaFuncSetAttribute(gemm16_kernel<3>, cudaFuncAttributeMaxDynamicSharedMemorySize, GSMEM);
    cudaFuncSetAttribute(attn_tc_kernel,   cudaFuncAttributeMaxDynamicSharedMemorySize, ASMEM);

    // --- prepack weights (fp16) ---
    wconv_kernel<<<(CQKV * CH / 4 + 255) / 256, 256>>>(qkv_w, wqkv, CQKV * CH / 4);
    prepack_proj_kernel<<<(CH * C3 + 255) / 256, 256>>>(proj_w, proj_b, focus);
    wconv_kernel<<<(MLPH * CH / 4 + 255) / 256, 256>>>(mlp_w1, w1, MLPH * CH / 4);
    wconv_kernel<<<(CH * MLPH / 4 + 255) / 256, 256>>>(mlp_w2, w2, CH * MLPH / 4);

    // 1) h = LN1(x) -> fp16
    ln_kernel<<<MROWS, 256>>>(x, ln1_w, ln1_b, h16);
    // 2) qkv16 = h @ qkv_w^T, scattered to head-major planes
    gemm16_kernel<3><<<dim3(CQKV / 128, MROWS / 128), 256, GSMEM>>>(
        h16, wqkv, nullptr, nullptr, qkv16, MROWS, CQKV, CH);
    // 3) attention (head-major planes in, C3-major ocat out)
    attn_tc_kernel<<<dim3(SEQ / 128, BB * NH, 3), 256, ASMEM>>>(qkv16, focus, ocat16);
    // 4) x2 = x + ocat @ projw^T + bias2
    gemm16_kernel<1><<<dim3(CH / 128, MROWS / 128), 256, GSMEM>>>(
        ocat16, wproj, b2, x, x2, MROWS, CH, C3);
    // 5) h2 = LN2(x2) -> fp16
    ln_kernel<<<MROWS, 256>>>(x2, ln2_w, ln2_b, h16);
    // 6) mlp16 = gelu(h2 @ w1^T + b1)
    gemm16_kernel<2><<<dim3(MLPH / 128, MROWS / 128), 256, GSMEM>>>(
        h16, w1, mlp_b1, nullptr, mlp16, MROWS, MLPH, CH);
    // 7) out = x2 + mlp16 @ w2^T + b2
    gemm16_kernel<1><<<dim3(CH / 128, MROWS / 128), 256, GSMEM>>>(
        mlp16, w2, mlp_b2, x2, out, MROWS, CH, MLPH);
}